// round 9
// baseline (speedup 1.0000x reference)
#include <cuda_runtime.h>
#include <cuda_bf16.h>
#include <cstdint>
#include <cstddef>

#define NWSEQ 1024
#define TW    64
#define MWORD (NWSEQ*TW)
#define NDOC  32
#define TSENT 32
#define MSENT (NDOC*TSENT)
#define HD2   512
#define HD3   768
#define EDIM  200

typedef unsigned long long ull;

// scratch (device globals; allocation-free rule)
__device__ float g_xg [2ull*MWORD*HD3];     // word input gates; later partial scores
__device__ float g_h  [(size_t)MWORD*HD2];  // word BiGRU hidden
__device__ float g_sents[(size_t)MSENT*HD2];
__device__ float g_xg2[2ull*MSENT*HD3];
__device__ float g_h2 [(size_t)MSENT*HD2];
__device__ float4 g_whp [2*256*256 + 1024]; // repacked word Wh [dir][k][j]{r,z,n,0} + prefetch pad
__device__ float4 g_whp2[2*256*256 + 1024];

__device__ __forceinline__ ull pk2(float lo, float hi){
    ull r; asm("mov.b64 %0, {%1,%2};" : "=l"(r) : "f"(lo), "f"(hi)); return r;
}
__device__ __forceinline__ float2 upk2(ull v){
    float2 f; asm("mov.b64 {%0,%1}, %2;" : "=f"(f.x), "=f"(f.y) : "l"(v)); return f;
}
__device__ __forceinline__ ull fma2(ull a, ull b, ull c){
    ull d; asm("fma.rn.f32x2 %0, %1, %2, %3;" : "=l"(d) : "l"(a), "l"(b), "l"(c)); return d;
}
__device__ __forceinline__ float fsig(float x){ return 1.0f/(1.0f + __expf(-x)); }
__device__ __forceinline__ float ftanh(float x){ return 1.0f - 2.0f/(__expf(2.0f*x) + 1.0f); }

// ---- bf16 split helpers ----
__device__ __forceinline__ void cvt_pair(float a, float b, uint32_t& hi, uint32_t& lo){
    __nv_bfloat16 ha = __float2bfloat16_rn(a), hb = __float2bfloat16_rn(b);
    float la = a - __bfloat162float(ha);
    float lb = b - __bfloat162float(hb);
    __nv_bfloat162 ph = __halves2bfloat162(ha, hb);
    __nv_bfloat162 pl = __halves2bfloat162(__float2bfloat16_rn(la), __float2bfloat16_rn(lb));
    hi = *(uint32_t*)&ph; lo = *(uint32_t*)&pl;
}
__device__ __forceinline__ void ldsm4(uint32_t& r0, uint32_t& r1, uint32_t& r2, uint32_t& r3, uint32_t addr){
    asm volatile("ldmatrix.sync.aligned.m8n8.x4.shared.b16 {%0,%1,%2,%3}, [%4];"
        : "=r"(r0), "=r"(r1), "=r"(r2), "=r"(r3) : "r"(addr));
}
__device__ __forceinline__ void ldsm4t(uint32_t& r0, uint32_t& r1, uint32_t& r2, uint32_t& r3, uint32_t addr){
    asm volatile("ldmatrix.sync.aligned.m8n8.x4.trans.shared.b16 {%0,%1,%2,%3}, [%4];"
        : "=r"(r0), "=r"(r1), "=r"(r2), "=r"(r3) : "r"(addr));
}
__device__ __forceinline__ void mma16816(float* d, uint32_t a0, uint32_t a1, uint32_t a2, uint32_t a3,
                                         uint32_t b0, uint32_t b1){
    asm volatile("mma.sync.aligned.m16n8k16.row.col.f32.bf16.bf16.f32 "
        "{%0,%1,%2,%3}, {%4,%5,%6,%7}, {%8,%9}, {%0,%1,%2,%3};"
        : "+f"(d[0]), "+f"(d[1]), "+f"(d[2]), "+f"(d[3])
        : "r"(a0), "r"(a1), "r"(a2), "r"(a3), "r"(b0), "r"(b1));
}

// ---------------------------------------------------------------------------
// Repack Wh [256][768] -> float4[dir][k][j] = {Wr, Wz, Wn, 0}
// ---------------------------------------------------------------------------
__global__ void repack_wh_kernel(const float* __restrict__ Whf,
                                 const float* __restrict__ Whb,
                                 float4* __restrict__ whp){
    int k = blockIdx.x, d = blockIdx.y, j = threadIdx.x;
    const float* Wh = d ? Whb : Whf;
    float4 v;
    v.x = Wh[(size_t)k*HD3 + j];
    v.y = Wh[(size_t)k*HD3 + 256 + j];
    v.z = Wh[(size_t)k*HD3 + 512 + j];
    v.w = 0.f;
    whp[((size_t)d*256 + k)*256 + j] = v;
}

// ---------------------------------------------------------------------------
// bf16-split tensor-core GEMM. Block tile 128(M) x 64(N), k-tile 32.
// 8 warps: warp w computes rows [16w,16w+16), all 64 cols.
// B fragments via ldmatrix.x4.trans (2 n-tiles per instruction).
//  SCORE=0: out[dir][m][j] = A[row(m)] @ W_dir + bias_dir  (ldw = nyPerDir*64)
//  SCORE=1: out[jb*M + m] = sum_j tanh((A@W+b)[m][j])*ctx[j] over this tile's 64 j
// grid = (M/128, (SCORE?1:2)*nyPerDir)
// ---------------------------------------------------------------------------
#define ASTR 40   // ushorts per A smem row (32 + pad)
#define BSTR 72   // ushorts per B smem row (64 + pad)
template<bool SCORE>
__global__ __launch_bounds__(256,2) void mma_gemm_kernel(
    const float* __restrict__ A, const int* __restrict__ gather, int K,
    const float* __restrict__ Wf, const float* __restrict__ Wb,
    const float* __restrict__ bf_, const float* __restrict__ bb_,
    const float* __restrict__ ctx,
    float* __restrict__ out, int M, int nyPerDir)
{
    __shared__ __align__(16) unsigned short sAhi[128*ASTR], sAlo[128*ASTR];
    __shared__ __align__(16) unsigned short sBhi[32*BSTR],  sBlo[32*BSTR];
    int tid = threadIdx.x;
    int w = tid >> 5, lane = tid & 31;
    int g = lane >> 2, t4 = lane & 3;
    int m0 = blockIdx.x * 128;
    int dir = blockIdx.y / nyPerDir;
    int jb  = blockIdx.y % nyPerDir;
    int j0  = jb * 64;
    int ldw = nyPerDir * 64;
    const float* W    = dir ? Wb : Wf;
    const float* bias = dir ? bb_ : bf_;

    // loaders
    int arow = tid >> 1, ahalf = tid & 1;
    int ridx = m0 + arow;
    const float* ap = A + (size_t)(gather ? gather[ridx] : ridx) * K;
    int bkr = tid >> 3, bc0 = (tid & 7) * 8;
    const float* bp = W + (size_t)bkr * ldw + j0 + bc0;

    float acc[8][4];
#pragma unroll
    for (int n = 0; n < 8; n++){ acc[n][0]=acc[n][1]=acc[n][2]=acc[n][3]=0.f; }

    uint32_t sAhiB = (uint32_t)__cvta_generic_to_shared(sAhi);
    uint32_t sAloB = (uint32_t)__cvta_generic_to_shared(sAlo);
    uint32_t sBhiB = (uint32_t)__cvta_generic_to_shared(sBhi);
    uint32_t sBloB = (uint32_t)__cvta_generic_to_shared(sBlo);
    uint32_t aOff = ((w*16 + (lane & 15)) * ASTR + (lane >> 4) * 8) * 2;
    uint32_t bT = ((lane & 15) * BSTR + (lane >> 4) * 8) * 2;

    int nt = (K + 31) / 32;
    float ar[16], br[8];

    // preload tile 0
    {
#pragma unroll
        for (int q = 0; q < 4; q++){
            int kk = ahalf*16 + q*4;
            if (kk + 3 < K) { float4 f = *(const float4*)&ap[kk];
                ar[q*4]=f.x; ar[q*4+1]=f.y; ar[q*4+2]=f.z; ar[q*4+3]=f.w; }
            else {
#pragma unroll
                for (int e = 0; e < 4; e++) ar[q*4+e] = (kk+e < K) ? ap[kk+e] : 0.f;
            }
        }
        if (bkr < K){ float4 f0 = *(const float4*)&bp[0]; float4 f1 = *(const float4*)&bp[4];
            br[0]=f0.x;br[1]=f0.y;br[2]=f0.z;br[3]=f0.w;br[4]=f1.x;br[5]=f1.y;br[6]=f1.z;br[7]=f1.w; }
        else { for (int e=0;e<8;e++) br[e]=0.f; }
    }

    for (int t = 0; t < nt; t++) {
        __syncthreads();
        // convert + store to smem
        {
            int abase = arow * ASTR + ahalf * 16;
#pragma unroll
            for (int p = 0; p < 8; p++){
                uint32_t hi, lo;
                cvt_pair(ar[2*p], ar[2*p+1], hi, lo);
                *(uint32_t*)&sAhi[abase + 2*p] = hi;
                *(uint32_t*)&sAlo[abase + 2*p] = lo;
            }
            int bbase = bkr * BSTR + bc0;
#pragma unroll
            for (int p = 0; p < 4; p++){
                uint32_t hi, lo;
                cvt_pair(br[2*p], br[2*p+1], hi, lo);
                *(uint32_t*)&sBhi[bbase + 2*p] = hi;
                *(uint32_t*)&sBlo[bbase + 2*p] = lo;
            }
        }
        __syncthreads();
        // prefetch next tile
        if (t + 1 < nt) {
            int k0 = (t + 1) * 32;
#pragma unroll
            for (int q = 0; q < 4; q++){
                int kk = k0 + ahalf*16 + q*4;
                if (kk + 3 < K) { float4 f = *(const float4*)&ap[kk];
                    ar[q*4]=f.x; ar[q*4+1]=f.y; ar[q*4+2]=f.z; ar[q*4+3]=f.w; }
                else {
#pragma unroll
                    for (int e = 0; e < 4; e++) ar[q*4+e] = (kk+e < K) ? ap[kk+e] : 0.f;
                }
            }
            if (k0 + bkr < K){ const float* b2 = bp + (size_t)k0 * ldw;
                float4 f0 = *(const float4*)&b2[0]; float4 f1 = *(const float4*)&b2[4];
                br[0]=f0.x;br[1]=f0.y;br[2]=f0.z;br[3]=f0.w;br[4]=f1.x;br[5]=f1.y;br[6]=f1.z;br[7]=f1.w; }
            else { for (int e=0;e<8;e++) br[e]=0.f; }
        }
        // mma on current smem tile: two k16 halves
#pragma unroll
        for (int h = 0; h < 2; h++){
            uint32_t ah0,ah1,ah2,ah3, al0,al1,al2,al3;
            ldsm4(ah0,ah1,ah2,ah3, sAhiB + aOff + h*32);
            ldsm4(al0,al1,al2,al3, sAloB + aOff + h*32);
#pragma unroll
            for (int np = 0; np < 4; np++){
                uint32_t ba = bT + h*16*BSTR*2 + np*32;
                uint32_t bh0,bh1,bh2,bh3, bl0,bl1,bl2,bl3;
                ldsm4t(bh0,bh1,bh2,bh3, sBhiB + ba);
                ldsm4t(bl0,bl1,bl2,bl3, sBloB + ba);
                mma16816(acc[2*np],   ah0,ah1,ah2,ah3, bh0,bh1);
                mma16816(acc[2*np],   ah0,ah1,ah2,ah3, bl0,bl1);
                mma16816(acc[2*np],   al0,al1,al2,al3, bh0,bh1);
                mma16816(acc[2*np+1], ah0,ah1,ah2,ah3, bh2,bh3);
                mma16816(acc[2*np+1], ah0,ah1,ah2,ah3, bl2,bl3);
                mma16816(acc[2*np+1], al0,al1,al2,al3, bh2,bh3);
            }
        }
    }

    // epilogue
    if (!SCORE) {
        float* od = out + (size_t)dir * M * ldw;
        int r0 = m0 + w*16 + g;
#pragma unroll
        for (int n = 0; n < 8; n++){
            int c = j0 + n*8 + t4*2;
            float b0 = __ldg(&bias[c]), b1 = __ldg(&bias[c+1]);
            float2 o0{acc[n][0] + b0, acc[n][1] + b1};
            float2 o1{acc[n][2] + b0, acc[n][3] + b1};
            *(float2*)&od[(size_t)r0 * ldw + c]       = o0;
            *(float2*)&od[(size_t)(r0+8) * ldw + c]   = o1;
        }
    } else {
        float s0 = 0.f, s1 = 0.f;
#pragma unroll
        for (int n = 0; n < 8; n++){
            int c = j0 + n*8 + t4*2;
            float b0 = __ldg(&bias[c]), b1 = __ldg(&bias[c+1]);
            float c0 = __ldg(&ctx[c]),  c1 = __ldg(&ctx[c+1]);
            s0 += ftanh(acc[n][0] + b0)*c0 + ftanh(acc[n][1] + b1)*c1;
            s1 += ftanh(acc[n][2] + b0)*c0 + ftanh(acc[n][3] + b1)*c1;
        }
        s0 += __shfl_xor_sync(0xffffffffu, s0, 1); s0 += __shfl_xor_sync(0xffffffffu, s0, 2);
        s1 += __shfl_xor_sync(0xffffffffu, s1, 1); s1 += __shfl_xor_sync(0xffffffffu, s1, 2);
        if (t4 == 0){
            int r0 = m0 + w*16 + g;
            out[(size_t)jb * M + r0]     = s0;
            out[(size_t)jb * M + r0 + 8] = s1;
        }
    }
}

// ---------------------------------------------------------------------------
// Word GRU scan, 512 threads: G=16 seqs/block, two thread-halves share the
// same weight stream (tid & tid+256 own hidden unit j=tid&255 -> L1/MSHR
// dedup halves L2 traffic) but cover disjoint 8-seq halves. Per-thread state
// identical to the proven G=8 kernel. grid = (NS/16)*2, single wave.
// ---------------------------------------------------------------------------
template<int T>
__global__ __launch_bounds__(512,1) void gru_scan512_kernel(
    const float* __restrict__ xg,   // [2][NS*T][768]
    float* __restrict__ hout,       // [NS*T][512]
    const float4* __restrict__ whp, // [2][256][256] (+pad)
    const float* __restrict__ bhf, const float* __restrict__ bhb, int NS)
{
    constexpr int G = 16, PG = 8, P = 4;
    __shared__ __align__(16) float sh[2][256][G];
    int tid = threadIdx.x;
    int j = tid & 255;
    int half = tid >> 8;          // 0 or 1
    int hb = half * PG;           // column base in sh
    int gpd = NS / G;
    int d  = blockIdx.x / gpd;
    int n0 = (blockIdx.x % gpd) * G + hb;   // this thread's first sequence
    const float* bh = d ? bhb : bhf;
    const float4* Wp = whp + (size_t)d * 256 * 256;
    const float* xgd = xg + (size_t)d * NS * T * HD3;
    float bhr = bh[j], bhz = bh[256 + j], bhn = bh[512 + j];
    float hprev[PG];
#pragma unroll
    for (int gg = 0; gg < PG; gg++){ hprev[gg] = 0.f; sh[0][j][hb + gg] = 0.f; }
    __syncthreads();

    int cur = 0;
    for (int tt = 0; tt < T; tt++) {
        int t = d ? (T - 1 - tt) : tt;
        ull ar[P], az[P], an[P];
#pragma unroll
        for (int p = 0; p < P; p++){
            ar[p] = pk2(bhr, bhr); az[p] = pk2(bhz, bhz); an[p] = pk2(bhn, bhn);
        }
        float4 w = Wp[j];
#pragma unroll 8
        for (int k = 0; k < 256; k++) {
            float4 wnext = Wp[(size_t)(k + 1) * 256 + j];   // pad row beyond end
            ull wr2 = pk2(w.x, w.x), wz2 = pk2(w.y, w.y), wn2 = pk2(w.z, w.z);
#pragma unroll
            for (int p = 0; p < P; p++){
                ull h2 = *(const ull*)&sh[cur][k][hb + 2*p];
                ar[p] = fma2(wr2, h2, ar[p]);
                az[p] = fma2(wz2, h2, az[p]);
                an[p] = fma2(wn2, h2, an[p]);
            }
            w = wnext;
        }
        int nxt = cur ^ 1;
        float hnew[PG];
#pragma unroll
        for (int p = 0; p < P; p++){
            float2 fr = upk2(ar[p]), fz = upk2(az[p]), fn = upk2(an[p]);
#pragma unroll
            for (int e = 0; e < 2; e++){
                int gg = 2*p + e;
                const float* xp = xgd + ((size_t)(n0 + gg) * T + t) * HD3;
                float hr = e ? fr.y : fr.x, hz = e ? fz.y : fz.x, hn = e ? fn.y : fn.x;
                float r = fsig(xp[j] + hr), z = fsig(xp[256 + j] + hz);
                float n = ftanh(xp[512 + j] + r * hn);
                hnew[gg] = (1.f - z) * n + z * hprev[gg];
            }
        }
#pragma unroll
        for (int gg = 0; gg < PG; gg++){
            hprev[gg] = hnew[gg];
            sh[nxt][j][hb + gg] = hnew[gg];
            hout[((size_t)(n0 + gg) * T + t) * HD2 + d * 256 + j] = hnew[gg];
        }
        cur = nxt;
        __syncthreads();
    }
}

// ---------------------------------------------------------------------------
// Sentence GRU scan (small): G seqs/block, 256 threads — unchanged.
// ---------------------------------------------------------------------------
template<int T, int G>
__global__ __launch_bounds__(256,2) void gru_scan_kernel(
    const float* __restrict__ xg,
    float* __restrict__ hout,
    const float4* __restrict__ whp,
    const float* __restrict__ bhf, const float* __restrict__ bhb, int NS)
{
    constexpr int P = G / 2;
    __shared__ __align__(16) float sh[2][256][G];
    int j = threadIdx.x;
    int gpd = NS / G;
    int d  = blockIdx.x / gpd;
    int n0 = (blockIdx.x % gpd) * G;
    const float* bh = d ? bhb : bhf;
    const float4* Wp = whp + (size_t)d * 256 * 256;
    const float* xgd = xg + (size_t)d * NS * T * HD3;
    float bhr = bh[j], bhz = bh[256 + j], bhn = bh[512 + j];
    float hprev[G];
#pragma unroll
    for (int gg = 0; gg < G; gg++){ hprev[gg] = 0.f; sh[0][j][gg] = 0.f; }
    __syncthreads();

    int cur = 0;
    for (int tt = 0; tt < T; tt++) {
        int t = d ? (T - 1 - tt) : tt;
        ull ar[P], az[P], an[P];
#pragma unroll
        for (int p = 0; p < P; p++){
            ar[p] = pk2(bhr, bhr); az[p] = pk2(bhz, bhz); an[p] = pk2(bhn, bhn);
        }
        float4 w = Wp[j];
#pragma unroll 8
        for (int k = 0; k < 256; k++) {
            float4 wnext = Wp[(size_t)(k + 1) * 256 + j];
            ull wr2 = pk2(w.x, w.x), wz2 = pk2(w.y, w.y), wn2 = pk2(w.z, w.z);
#pragma unroll
            for (int p = 0; p < P; p++){
                ull h2 = *(const ull*)&sh[cur][k][2*p];
                ar[p] = fma2(wr2, h2, ar[p]);
                az[p] = fma2(wz2, h2, az[p]);
                an[p] = fma2(wn2, h2, an[p]);
            }
            w = wnext;
        }
        int nxt = cur ^ 1;
        float hnew[G];
#pragma unroll
        for (int p = 0; p < P; p++){
            float2 fr = upk2(ar[p]), fz = upk2(az[p]), fn = upk2(an[p]);
#pragma unroll
            for (int e = 0; e < 2; e++){
                int gg = 2*p + e;
                const float* xp = xgd + ((size_t)(n0 + gg) * T + t) * HD3;
                float hr = e ? fr.y : fr.x, hz = e ? fz.y : fz.x, hn = e ? fn.y : fn.x;
                float r = fsig(xp[j] + hr), z = fsig(xp[256 + j] + hz);
                float n = ftanh(xp[512 + j] + r * hn);
                hnew[gg] = (1.f - z) * n + z * hprev[gg];
            }
        }
#pragma unroll
        for (int gg = 0; gg < G; gg++){
            hprev[gg] = hnew[gg];
            sh[nxt][j][gg] = hnew[gg];
            hout[((size_t)(n0 + gg) * T + t) * HD2 + d * 256 + j] = hnew[gg];
        }
        cur = nxt;
        __syncthreads();
    }
}

// ---------------------------------------------------------------------------
// Attention epilogue: sum partial scores -> sparsemax -> weighted sum of h.
// ---------------------------------------------------------------------------
template<int T, bool FINAL>
__global__ __launch_bounds__(256) void attn_epi_kernel(
    const float* __restrict__ part,   // [8][nseq*T] partial scores
    const float* __restrict__ h,      // [nseq*T][512]
    float* __restrict__ outv,
    const float* __restrict__ outW,
    const float* __restrict__ outb,
    float* __restrict__ outFinal,
    int Mtot)
{
    __shared__ float sScore[T], sX[T], sSrt[T], sAtt[T];
    __shared__ float sTau, sMax;
    __shared__ float sDoc[512];
    int tid = threadIdx.x;
    int n = blockIdx.x;
    const float* hbase = h + (size_t)n * T * HD2;

    if (tid < T) {
        float s = 0.f;
#pragma unroll
        for (int jb = 0; jb < 8; jb++) s += part[(size_t)jb * Mtot + n * T + tid];
        sScore[tid] = s;
    }
    __syncthreads();
    if (tid == 0) {
        float mx = sScore[0];
        for (int t = 1; t < T; t++) mx = fmaxf(mx, sScore[t]);
        sMax = mx;
    }
    __syncthreads();
    if (tid < T) {
        float x = sScore[tid] - sMax;
        sX[tid] = x;
        int rank = 0;
        for (int u = 0; u < T; u++){
            float xu = sScore[u] - sMax;
            if (xu > x || (xu == x && u < tid)) rank++;
        }
        sSrt[rank] = x;
    }
    __syncthreads();
    if (tid == 0) {
        float cs = -1.f; int supp = 0; float csAt = 0.f;
        for (int k = 0; k < T; k++){
            cs += sSrt[k];
            if ((float)(k + 1) * sSrt[k] > cs) { supp = k + 1; csAt = cs; }
        }
        sTau = csAt / (float)supp;
    }
    __syncthreads();
    if (tid < T) sAtt[tid] = fmaxf(sX[tid] - sTau, 0.f);
    __syncthreads();
    {
        int jj = tid * 2;
        float ax = 0.f, ay = 0.f;
#pragma unroll 8
        for (int t = 0; t < T; t++){
            float2 hv = *(const float2*)&hbase[(size_t)t * HD2 + jj];
            float a = sAtt[t];
            ax += a * hv.x; ay += a * hv.y;
        }
        if (FINAL){ sDoc[jj] = ax; sDoc[jj + 1] = ay; }
        else { float2 o{ax, ay}; *(float2*)&outv[(size_t)n * HD2 + jj] = o; }
    }
    if (FINAL) {
        __syncthreads();
        if (tid < 10) {
            float s = outb[tid];
            for (int jj2 = 0; jj2 < 512; jj2++) s += sDoc[jj2] * outW[jj2 * 10 + tid];
            outFinal[n * 10 + tid] = s;
        }
    }
}

extern "C" void kernel_launch(void* const* d_in, const int* in_sizes, int n_in,
                              void* d_out, int out_size) {
    const int*   tokens  = (const int*)  d_in[0];
    const float* emb     = (const float*)d_in[1];
    const float* w_Wx_f  = (const float*)d_in[2];
    const float* w_Wh_f  = (const float*)d_in[3];
    const float* w_bx_f  = (const float*)d_in[4];
    const float* w_bh_f  = (const float*)d_in[5];
    const float* w_Wx_b  = (const float*)d_in[6];
    const float* w_Wh_b  = (const float*)d_in[7];
    const float* w_bx_b  = (const float*)d_in[8];
    const float* w_bh_b  = (const float*)d_in[9];
    const float* w_lin_W = (const float*)d_in[10];
    const float* w_lin_b = (const float*)d_in[11];
    const float* w_ctx   = (const float*)d_in[12];
    const float* s_Wx_f  = (const float*)d_in[13];
    const float* s_Wh_f  = (const float*)d_in[14];
    const float* s_bx_f  = (const float*)d_in[15];
    const float* s_bh_f  = (const float*)d_in[16];
    const float* s_Wx_b  = (const float*)d_in[17];
    const float* s_Wh_b  = (const float*)d_in[18];
    const float* s_bx_b  = (const float*)d_in[19];
    const float* s_bh_b  = (const float*)d_in[20];
    const float* s_lin_W = (const float*)d_in[21];
    const float* s_lin_b = (const float*)d_in[22];
    const float* s_ctx   = (const float*)d_in[23];
    const float* out_W   = (const float*)d_in[24];
    const float* out_b   = (const float*)d_in[25];
    float* out = (float*)d_out;

    float *p_xg, *p_h, *p_sents, *p_xg2, *p_h2;
    float4 *p_whp, *p_whp2;
    cudaGetSymbolAddress((void**)&p_xg,   g_xg);
    cudaGetSymbolAddress((void**)&p_h,    g_h);
    cudaGetSymbolAddress((void**)&p_sents,g_sents);
    cudaGetSymbolAddress((void**)&p_xg2,  g_xg2);
    cudaGetSymbolAddress((void**)&p_h2,   g_h2);
    cudaGetSymbolAddress((void**)&p_whp,  g_whp);
    cudaGetSymbolAddress((void**)&p_whp2, g_whp2);

    // 0. repack recurrent weights
    repack_wh_kernel<<<dim3(256,2), 256>>>(w_Wh_f, w_Wh_b, p_whp);
    repack_wh_kernel<<<dim3(256,2), 256>>>(s_Wh_f, s_Wh_b, p_whp2);
    // 1. word input gates (embedding gather fused), both dirs (tensor cores)
    mma_gemm_kernel<false><<<dim3(MWORD/128, 24), 256>>>(
        emb, tokens, EDIM, w_Wx_f, w_Wx_b, w_bx_f, w_bx_b, nullptr, p_xg, MWORD, 12);
    // 2. word BiGRU scan (512 threads, G=16 with weight-stream sharing)
    gru_scan512_kernel<TW><<<(NWSEQ/16)*2, 512>>>(
        p_xg, p_h, p_whp, w_bh_f, w_bh_b, NWSEQ);
    // 3. word rep GEMM fused into scores (tensor cores; partials into g_xg)
    mma_gemm_kernel<true><<<dim3(MWORD/128, 8), 256>>>(
        p_h, nullptr, HD2, w_lin_W, w_lin_W, w_lin_b, w_lin_b, w_ctx, p_xg, MWORD, 8);
    // 4. word attention epilogue -> sentence vectors
    attn_epi_kernel<TW, false><<<NWSEQ, 256>>>(
        p_xg, p_h, p_sents, nullptr, nullptr, nullptr, MWORD);
    // 5. sentence input gates
    mma_gemm_kernel<false><<<dim3(MSENT/128, 24), 256>>>(
        p_sents, nullptr, HD2, s_Wx_f, s_Wx_b, s_bx_f, s_bx_b, nullptr, p_xg2, MSENT, 12);
    // 6. sentence BiGRU scan
    gru_scan_kernel<TSENT, 2><<<(NDOC/2)*2, 256>>>(
        p_xg2, p_h2, p_whp2, s_bh_f, s_bh_b, NDOC);
    // 7. sentence rep+score GEMM (partials into g_xg2)
    mma_gemm_kernel<true><<<dim3(MSENT/128, 8), 256>>>(
        p_h2, nullptr, HD2, s_lin_W, s_lin_W, s_lin_b, s_lin_b, s_ctx, p_xg2, MSENT, 8);
    // 8. sentence attention + final classifier
    attn_epi_kernel<TSENT, true><<<NDOC, 256>>>(
        p_xg2, p_h2, nullptr, out_W, out_b, out, MSENT);
}

// round 10
// speedup vs baseline: 1.0741x; 1.0741x over previous
#include <cuda_runtime.h>
#include <cuda_bf16.h>
#include <cstdint>
#include <cstddef>

#define NWSEQ 1024
#define TW    64
#define MWORD (NWSEQ*TW)
#define NDOC  32
#define TSENT 32
#define MSENT (NDOC*TSENT)
#define HD2   512
#define HD3   768
#define EDIM  200
#define VMAX  50000
#define EKP   224      // emb K padded to mult of 32

typedef unsigned long long ull;
typedef unsigned short u16;

// fp32 scratch
__device__ float g_xg [2ull*MWORD*HD3];
__device__ float g_h  [(size_t)MWORD*HD2];
__device__ float g_sents[(size_t)MSENT*HD2];
__device__ float g_xg2[2ull*MSENT*HD3];
__device__ float g_h2 [(size_t)MSENT*HD2];
__device__ float4 g_whp [2*256*256 + 1024];
__device__ float4 g_whp2[2*256*256 + 1024];
// bf16-split planes (pre-converted once per launch)
__device__ __nv_bfloat16 g_embC_hi[(size_t)VMAX*EKP], g_embC_lo[(size_t)VMAX*EKP];
__device__ __nv_bfloat16 g_wxC_hi [2*EKP*HD3],  g_wxC_lo [2*EKP*HD3];
__device__ __nv_bfloat16 g_linC_hi[HD2*HD2],    g_linC_lo[HD2*HD2];
__device__ __nv_bfloat16 g_swxC_hi[2*HD2*HD3],  g_swxC_lo[2*HD2*HD3];
__device__ __nv_bfloat16 g_slinC_hi[HD2*HD2],   g_slinC_lo[HD2*HD2];
__device__ __nv_bfloat16 g_hb_hi[(size_t)MWORD*HD2], g_hb_lo[(size_t)MWORD*HD2];
__device__ __nv_bfloat16 g_sb_hi[(size_t)MSENT*HD2], g_sb_lo[(size_t)MSENT*HD2];
__device__ __nv_bfloat16 g_h2b_hi[(size_t)MSENT*HD2], g_h2b_lo[(size_t)MSENT*HD2];

__device__ __forceinline__ ull pk2(float lo, float hi){
    ull r; asm("mov.b64 %0, {%1,%2};" : "=l"(r) : "f"(lo), "f"(hi)); return r;
}
__device__ __forceinline__ float2 upk2(ull v){
    float2 f; asm("mov.b64 {%0,%1}, %2;" : "=f"(f.x), "=f"(f.y) : "l"(v)); return f;
}
__device__ __forceinline__ ull fma2(ull a, ull b, ull c){
    ull d; asm("fma.rn.f32x2 %0, %1, %2, %3;" : "=l"(d) : "l"(a), "l"(b), "l"(c)); return d;
}
__device__ __forceinline__ float fsig(float x){ return 1.0f/(1.0f + __expf(-x)); }
__device__ __forceinline__ float ftanh(float x){ return 1.0f - 2.0f/(__expf(2.0f*x) + 1.0f); }

__device__ __forceinline__ void ldsm4(uint32_t& r0, uint32_t& r1, uint32_t& r2, uint32_t& r3, uint32_t addr){
    asm volatile("ldmatrix.sync.aligned.m8n8.x4.shared.b16 {%0,%1,%2,%3}, [%4];"
        : "=r"(r0), "=r"(r1), "=r"(r2), "=r"(r3) : "r"(addr));
}
__device__ __forceinline__ void ldsm4t(uint32_t& r0, uint32_t& r1, uint32_t& r2, uint32_t& r3, uint32_t addr){
    asm volatile("ldmatrix.sync.aligned.m8n8.x4.trans.shared.b16 {%0,%1,%2,%3}, [%4];"
        : "=r"(r0), "=r"(r1), "=r"(r2), "=r"(r3) : "r"(addr));
}
__device__ __forceinline__ void mma16816(float* d, uint32_t a0, uint32_t a1, uint32_t a2, uint32_t a3,
                                         uint32_t b0, uint32_t b1){
    asm volatile("mma.sync.aligned.m16n8k16.row.col.f32.bf16.bf16.f32 "
        "{%0,%1,%2,%3}, {%4,%5,%6,%7}, {%8,%9}, {%0,%1,%2,%3};"
        : "+f"(d[0]), "+f"(d[1]), "+f"(d[2]), "+f"(d[3])
        : "r"(a0), "r"(a1), "r"(a2), "r"(a3), "r"(b0), "r"(b1));
}

// ---------------------------------------------------------------------------
// Converters (run once per launch; numerically identical to the old on-the-fly path)
// ---------------------------------------------------------------------------
// Pad along columns: dst[row][KP], zero for col >= K
__global__ void conv_splitA_kernel(const float* __restrict__ src,
                                   __nv_bfloat16* __restrict__ hi, __nv_bfloat16* __restrict__ lo,
                                   int K, int KP, long long total){
    long long i = (long long)blockIdx.x * blockDim.x + threadIdx.x;
    if (i >= total) return;
    int col = (int)(i % KP);
    long long row = i / KP;
    float v = (col < K) ? src[row * K + col] : 0.f;
    __nv_bfloat16 h = __float2bfloat16_rn(v);
    hi[i] = h;
    lo[i] = __float2bfloat16_rn(v - __bfloat162float(h));
}
// Pad along rows: dst[KP][N], zero for k >= K
__global__ void conv_splitB_kernel(const float* __restrict__ src,
                                   __nv_bfloat16* __restrict__ hi, __nv_bfloat16* __restrict__ lo,
                                   int K, int KP, int N){
    long long i = (long long)blockIdx.x * blockDim.x + threadIdx.x;
    if (i >= (long long)KP * N) return;
    int n = (int)(i % N);
    int k = (int)(i / N);
    float v = (k < K) ? src[(size_t)k * N + n] : 0.f;
    __nv_bfloat16 h = __float2bfloat16_rn(v);
    hi[i] = h;
    lo[i] = __float2bfloat16_rn(v - __bfloat162float(h));
}

// ---------------------------------------------------------------------------
// Repack Wh [256][768] -> float4[dir][k][j] = {Wr, Wz, Wn, 0}
// ---------------------------------------------------------------------------
__global__ void repack_wh_kernel(const float* __restrict__ Whf,
                                 const float* __restrict__ Whb,
                                 float4* __restrict__ whp){
    int k = blockIdx.x, d = blockIdx.y, j = threadIdx.x;
    const float* Wh = d ? Whb : Whf;
    float4 v;
    v.x = Wh[(size_t)k*HD3 + j];
    v.y = Wh[(size_t)k*HD3 + 256 + j];
    v.z = Wh[(size_t)k*HD3 + 512 + j];
    v.w = 0.f;
    whp[((size_t)d*256 + k)*256 + j] = v;
}

// ---------------------------------------------------------------------------
// bf16-split tensor-core GEMM, pre-converted operands. 128x64 tile, k-tile 32.
// All conversions removed from the mainloop: load bf16 -> smem -> ldmatrix -> mma.
//  SCORE=0: out[dir][m][j] = A[row(m)] @ B_dir + bias_dir  (ldw = nyPerDir*64)
//  SCORE=1: out[jb*M + m] = sum_j tanh((A@B+b)[m][j])*ctx[j]
// grid = (M/128, (SCORE?1:2)*nyPerDir). KP multiple of 32 (zero-padded).
// ---------------------------------------------------------------------------
#define ASTR 40
#define BSTR 72
template<bool SCORE>
__global__ __launch_bounds__(256,2) void mma_gemm_bf16_kernel(
    const __nv_bfloat16* __restrict__ Ahi, const __nv_bfloat16* __restrict__ Alo,
    const int* __restrict__ gather, int KP,
    const __nv_bfloat16* __restrict__ Bhi, const __nv_bfloat16* __restrict__ Blo,
    const float* __restrict__ bf_, const float* __restrict__ bb_,
    const float* __restrict__ ctx,
    float* __restrict__ out, int M, int nyPerDir)
{
    __shared__ __align__(16) u16 sAhi[128*ASTR], sAlo[128*ASTR];
    __shared__ __align__(16) u16 sBhi[32*BSTR],  sBlo[32*BSTR];
    int tid = threadIdx.x;
    int w = tid >> 5, lane = tid & 31;
    int g = lane >> 2, t4 = lane & 3;
    int m0 = blockIdx.x * 128;
    int dir = blockIdx.y / nyPerDir;
    int jb  = blockIdx.y % nyPerDir;
    int j0  = jb * 64;
    int ldw = nyPerDir * 64;
    const __nv_bfloat16* Bh = Bhi + (size_t)dir * KP * ldw;
    const __nv_bfloat16* Bl = Blo + (size_t)dir * KP * ldw;
    const float* bias = dir ? bb_ : bf_;

    int arow = tid >> 1, ahalf = tid & 1;
    int ridx = m0 + arow;
    size_t aro = (size_t)(gather ? gather[ridx] : ridx) * KP + ahalf * 16;
    const __nv_bfloat16* aph = Ahi + aro;
    const __nv_bfloat16* apl = Alo + aro;
    int bkr = tid >> 3, bc0 = (tid & 7) * 8;
    size_t bo = (size_t)bkr * ldw + j0 + bc0;

    float acc[8][4];
#pragma unroll
    for (int n = 0; n < 8; n++){ acc[n][0]=acc[n][1]=acc[n][2]=acc[n][3]=0.f; }

    uint32_t sAhiB = (uint32_t)__cvta_generic_to_shared(sAhi);
    uint32_t sAloB = (uint32_t)__cvta_generic_to_shared(sAlo);
    uint32_t sBhiB = (uint32_t)__cvta_generic_to_shared(sBhi);
    uint32_t sBloB = (uint32_t)__cvta_generic_to_shared(sBlo);
    uint32_t aOff = ((w*16 + (lane & 15)) * ASTR + (lane >> 4) * 8) * 2;
    uint32_t bT = ((lane & 15) * BSTR + (lane >> 4) * 8) * 2;

    int nt = KP / 32;
    uint4 rah0, rah1, ral0, ral1, rbh, rbl;

    // preload tile 0
    rah0 = *(const uint4*)(aph);     rah1 = *(const uint4*)(aph + 8);
    ral0 = *(const uint4*)(apl);     ral1 = *(const uint4*)(apl + 8);
    rbh  = *(const uint4*)(Bh + bo); rbl  = *(const uint4*)(Bl + bo);

    for (int t = 0; t < nt; t++) {
        __syncthreads();
        {
            int abase = arow * ASTR + ahalf * 16;
            *(uint4*)&sAhi[abase]     = rah0;
            *(uint4*)&sAhi[abase + 8] = rah1;
            *(uint4*)&sAlo[abase]     = ral0;
            *(uint4*)&sAlo[abase + 8] = ral1;
            int bbase = bkr * BSTR + bc0;
            *(uint4*)&sBhi[bbase] = rbh;
            *(uint4*)&sBlo[bbase] = rbl;
        }
        __syncthreads();
        if (t + 1 < nt) {
            int k0 = (t + 1) * 32;
            rah0 = *(const uint4*)(aph + k0);     rah1 = *(const uint4*)(aph + k0 + 8);
            ral0 = *(const uint4*)(apl + k0);     ral1 = *(const uint4*)(apl + k0 + 8);
            size_t b2 = bo + (size_t)k0 * ldw;
            rbh = *(const uint4*)(Bh + b2);       rbl = *(const uint4*)(Bl + b2);
        }
#pragma unroll
        for (int h = 0; h < 2; h++){
            uint32_t ah0,ah1,ah2,ah3, al0,al1,al2,al3;
            ldsm4(ah0,ah1,ah2,ah3, sAhiB + aOff + h*32);
            ldsm4(al0,al1,al2,al3, sAloB + aOff + h*32);
#pragma unroll
            for (int np = 0; np < 4; np++){
                uint32_t ba = bT + h*16*BSTR*2 + np*32;
                uint32_t bh0,bh1,bh2,bh3, bl0,bl1,bl2,bl3;
                ldsm4t(bh0,bh1,bh2,bh3, sBhiB + ba);
                ldsm4t(bl0,bl1,bl2,bl3, sBloB + ba);
                mma16816(acc[2*np],   ah0,ah1,ah2,ah3, bh0,bh1);
                mma16816(acc[2*np],   ah0,ah1,ah2,ah3, bl0,bl1);
                mma16816(acc[2*np],   al0,al1,al2,al3, bh0,bh1);
                mma16816(acc[2*np+1], ah0,ah1,ah2,ah3, bh2,bh3);
                mma16816(acc[2*np+1], ah0,ah1,ah2,ah3, bl2,bl3);
                mma16816(acc[2*np+1], al0,al1,al2,al3, bh2,bh3);
            }
        }
    }

    if (!SCORE) {
        float* od = out + (size_t)dir * M * ldw;
        int r0 = m0 + w*16 + g;
#pragma unroll
        for (int n = 0; n < 8; n++){
            int c = j0 + n*8 + t4*2;
            float b0 = __ldg(&bias[c]), b1 = __ldg(&bias[c+1]);
            float2 o0{acc[n][0] + b0, acc[n][1] + b1};
            float2 o1{acc[n][2] + b0, acc[n][3] + b1};
            *(float2*)&od[(size_t)r0 * ldw + c]       = o0;
            *(float2*)&od[(size_t)(r0+8) * ldw + c]   = o1;
        }
    } else {
        float s0 = 0.f, s1 = 0.f;
#pragma unroll
        for (int n = 0; n < 8; n++){
            int c = j0 + n*8 + t4*2;
            float b0 = __ldg(&bias[c]), b1 = __ldg(&bias[c+1]);
            float c0 = __ldg(&ctx[c]),  c1 = __ldg(&ctx[c+1]);
            s0 += ftanh(acc[n][0] + b0)*c0 + ftanh(acc[n][1] + b1)*c1;
            s1 += ftanh(acc[n][2] + b0)*c0 + ftanh(acc[n][3] + b1)*c1;
        }
        s0 += __shfl_xor_sync(0xffffffffu, s0, 1); s0 += __shfl_xor_sync(0xffffffffu, s0, 2);
        s1 += __shfl_xor_sync(0xffffffffu, s1, 1); s1 += __shfl_xor_sync(0xffffffffu, s1, 2);
        if (t4 == 0){
            int r0 = m0 + w*16 + g;
            out[(size_t)jb * M + r0]     = s0;
            out[(size_t)jb * M + r0 + 8] = s1;
        }
    }
}

// ---------------------------------------------------------------------------
// GRU scan (R8-proven config: G=8, 256 threads, 2 blocks/SM). Additionally
// writes h in bf16-split planes for the downstream score GEMM.
// ---------------------------------------------------------------------------
template<int T, int G>
__global__ __launch_bounds__(256,2) void gru_scan_kernel(
    const float* __restrict__ xg,
    float* __restrict__ hout,
    __nv_bfloat16* __restrict__ hb_hi, __nv_bfloat16* __restrict__ hb_lo,
    const float4* __restrict__ whp,
    const float* __restrict__ bhf, const float* __restrict__ bhb, int NS)
{
    constexpr int P = G / 2;
    __shared__ __align__(16) float sh[2][256][G];
    int j = threadIdx.x;
    int gpd = NS / G;
    int d  = blockIdx.x / gpd;
    int n0 = (blockIdx.x % gpd) * G;
    const float* bh = d ? bhb : bhf;
    const float4* Wp = whp + (size_t)d * 256 * 256;
    const float* xgd = xg + (size_t)d * NS * T * HD3;
    float bhr = bh[j], bhz = bh[256 + j], bhn = bh[512 + j];
    float hprev[G];
#pragma unroll
    for (int gg = 0; gg < G; gg++){ hprev[gg] = 0.f; sh[0][j][gg] = 0.f; }
    __syncthreads();

    int cur = 0;
    for (int tt = 0; tt < T; tt++) {
        int t = d ? (T - 1 - tt) : tt;
        ull ar[P], az[P], an[P];
#pragma unroll
        for (int p = 0; p < P; p++){
            ar[p] = pk2(bhr, bhr); az[p] = pk2(bhz, bhz); an[p] = pk2(bhn, bhn);
        }
        float4 w = Wp[j];
#pragma unroll 8
        for (int k = 0; k < 256; k++) {
            float4 wnext = Wp[(size_t)(k + 1) * 256 + j];
            ull wr2 = pk2(w.x, w.x), wz2 = pk2(w.y, w.y), wn2 = pk2(w.z, w.z);
#pragma unroll
            for (int p = 0; p < P; p++){
                ull h2 = *(const ull*)&sh[cur][k][2*p];
                ar[p] = fma2(wr2, h2, ar[p]);
                az[p] = fma2(wz2, h2, az[p]);
                an[p] = fma2(wn2, h2, an[p]);
            }
            w = wnext;
        }
        int nxt = cur ^ 1;
        float hnew[G];
#pragma unroll
        for (int p = 0; p < P; p++){
            float2 fr = upk2(ar[p]), fz = upk2(az[p]), fn = upk2(an[p]);
#pragma unroll
            for (int e = 0; e < 2; e++){
                int gg = 2*p + e;
                const float* xp = xgd + ((size_t)(n0 + gg) * T + t) * HD3;
                float hr = e ? fr.y : fr.x, hz = e ? fz.y : fz.x, hn = e ? fn.y : fn.x;
                float r = fsig(xp[j] + hr), z = fsig(xp[256 + j] + hz);
                float n = ftanh(xp[512 + j] + r * hn);
                hnew[gg] = (1.f - z) * n + z * hprev[gg];
            }
        }
#pragma unroll
        for (int gg = 0; gg < G; gg++){
            float hv = hnew[gg];
            hprev[gg] = hv;
            sh[nxt][j][gg] = hv;
            size_t off = ((size_t)(n0 + gg) * T + t) * HD2 + d * 256 + j;
            hout[off] = hv;
            __nv_bfloat16 bhv = __float2bfloat16_rn(hv);
            hb_hi[off] = bhv;
            hb_lo[off] = __float2bfloat16_rn(hv - __bfloat162float(bhv));
        }
        cur = nxt;
        __syncthreads();
    }
}

// ---------------------------------------------------------------------------
// Attention epilogue: sum partial scores -> sparsemax -> weighted sum of h.
// ---------------------------------------------------------------------------
template<int T, bool FINAL>
__global__ __launch_bounds__(256) void attn_epi_kernel(
    const float* __restrict__ part,
    const float* __restrict__ h,
    float* __restrict__ outv,
    const float* __restrict__ outW,
    const float* __restrict__ outb,
    float* __restrict__ outFinal,
    int Mtot)
{
    __shared__ float sScore[T], sX[T], sSrt[T], sAtt[T];
    __shared__ float sTau, sMax;
    __shared__ float sDoc[512];
    int tid = threadIdx.x;
    int n = blockIdx.x;
    const float* hbase = h + (size_t)n * T * HD2;

    if (tid < T) {
        float s = 0.f;
#pragma unroll
        for (int jb = 0; jb < 8; jb++) s += part[(size_t)jb * Mtot + n * T + tid];
        sScore[tid] = s;
    }
    __syncthreads();
    if (tid == 0) {
        float mx = sScore[0];
        for (int t = 1; t < T; t++) mx = fmaxf(mx, sScore[t]);
        sMax = mx;
    }
    __syncthreads();
    if (tid < T) {
        float x = sScore[tid] - sMax;
        sX[tid] = x;
        int rank = 0;
        for (int u = 0; u < T; u++){
            float xu = sScore[u] - sMax;
            if (xu > x || (xu == x && u < tid)) rank++;
        }
        sSrt[rank] = x;
    }
    __syncthreads();
    if (tid == 0) {
        float cs = -1.f; int supp = 0; float csAt = 0.f;
        for (int k = 0; k < T; k++){
            cs += sSrt[k];
            if ((float)(k + 1) * sSrt[k] > cs) { supp = k + 1; csAt = cs; }
        }
        sTau = csAt / (float)supp;
    }
    __syncthreads();
    if (tid < T) sAtt[tid] = fmaxf(sX[tid] - sTau, 0.f);
    __syncthreads();
    {
        int jj = tid * 2;
        float ax = 0.f, ay = 0.f;
#pragma unroll 8
        for (int t = 0; t < T; t++){
            float2 hv = *(const float2*)&hbase[(size_t)t * HD2 + jj];
            float a = sAtt[t];
            ax += a * hv.x; ay += a * hv.y;
        }
        if (FINAL){ sDoc[jj] = ax; sDoc[jj + 1] = ay; }
        else { float2 o{ax, ay}; *(float2*)&outv[(size_t)n * HD2 + jj] = o; }
    }
    if (FINAL) {
        __syncthreads();
        if (tid < 10) {
            float s = outb[tid];
            for (int jj2 = 0; jj2 < 512; jj2++) s += sDoc[jj2] * outW[jj2 * 10 + tid];
            outFinal[n * 10 + tid] = s;
        }
    }
}

extern "C" void kernel_launch(void* const* d_in, const int* in_sizes, int n_in,
                              void* d_out, int out_size) {
    const int*   tokens  = (const int*)  d_in[0];
    const float* emb     = (const float*)d_in[1];
    const float* w_Wx_f  = (const float*)d_in[2];
    const float* w_Wh_f  = (const float*)d_in[3];
    const float* w_bx_f  = (const float*)d_in[4];
    const float* w_bh_f  = (const float*)d_in[5];
    const float* w_Wx_b  = (const float*)d_in[6];
    const float* w_Wh_b  = (const float*)d_in[7];
    const float* w_bx_b  = (const float*)d_in[8];
    const float* w_bh_b  = (const float*)d_in[9];
    const float* w_lin_W = (const float*)d_in[10];
    const float* w_lin_b = (const float*)d_in[11];
    const float* w_ctx   = (const float*)d_in[12];
    const float* s_Wx_f  = (const float*)d_in[13];
    const float* s_Wh_f  = (const float*)d_in[14];
    const float* s_bx_f  = (const float*)d_in[15];
    const float* s_bh_f  = (const float*)d_in[16];
    const float* s_Wx_b  = (const float*)d_in[17];
    const float* s_Wh_b  = (const float*)d_in[18];
    const float* s_bx_b  = (const float*)d_in[19];
    const float* s_bh_b  = (const float*)d_in[20];
    const float* s_lin_W = (const float*)d_in[21];
    const float* s_lin_b = (const float*)d_in[22];
    const float* s_ctx   = (const float*)d_in[23];
    const float* out_W   = (const float*)d_in[24];
    const float* out_b   = (const float*)d_in[25];
    float* out = (float*)d_out;

    int V = in_sizes[1] / EDIM;

    float *p_xg, *p_h, *p_sents, *p_xg2, *p_h2;
    float4 *p_whp, *p_whp2;
    __nv_bfloat16 *p_embH, *p_embL, *p_wxH, *p_wxL, *p_linH, *p_linL;
    __nv_bfloat16 *p_swxH, *p_swxL, *p_slinH, *p_slinL;
    __nv_bfloat16 *p_hbH, *p_hbL, *p_sbH, *p_sbL, *p_h2bH, *p_h2bL;
    cudaGetSymbolAddress((void**)&p_xg,   g_xg);
    cudaGetSymbolAddress((void**)&p_h,    g_h);
    cudaGetSymbolAddress((void**)&p_sents,g_sents);
    cudaGetSymbolAddress((void**)&p_xg2,  g_xg2);
    cudaGetSymbolAddress((void**)&p_h2,   g_h2);
    cudaGetSymbolAddress((void**)&p_whp,  g_whp);
    cudaGetSymbolAddress((void**)&p_whp2, g_whp2);
    cudaGetSymbolAddress((void**)&p_embH, g_embC_hi);  cudaGetSymbolAddress((void**)&p_embL, g_embC_lo);
    cudaGetSymbolAddress((void**)&p_wxH,  g_wxC_hi);   cudaGetSymbolAddress((void**)&p_wxL,  g_wxC_lo);
    cudaGetSymbolAddress((void**)&p_linH, g_linC_hi);  cudaGetSymbolAddress((void**)&p_linL, g_linC_lo);
    cudaGetSymbolAddress((void**)&p_swxH, g_swxC_hi);  cudaGetSymbolAddress((void**)&p_swxL, g_swxC_lo);
    cudaGetSymbolAddress((void**)&p_slinH,g_slinC_hi); cudaGetSymbolAddress((void**)&p_slinL,g_slinC_lo);
    cudaGetSymbolAddress((void**)&p_hbH,  g_hb_hi);    cudaGetSymbolAddress((void**)&p_hbL,  g_hb_lo);
    cudaGetSymbolAddress((void**)&p_sbH,  g_sb_hi);    cudaGetSymbolAddress((void**)&p_sbL,  g_sb_lo);
    cudaGetSymbolAddress((void**)&p_h2bH, g_h2b_hi);   cudaGetSymbolAddress((void**)&p_h2bL, g_h2b_lo);

    // 0. one-time conversions / repacks
    repack_wh_kernel<<<dim3(256,2), 256>>>(w_Wh_f, w_Wh_b, p_whp);
    repack_wh_kernel<<<dim3(256,2), 256>>>(s_Wh_f, s_Wh_b, p_whp2);
    {
        long long tot = (long long)V * EKP;
        conv_splitA_kernel<<<(unsigned)((tot + 255) / 256), 256>>>(emb, p_embH, p_embL, EDIM, EKP, tot);
    }
    conv_splitB_kernel<<<(EKP*HD3 + 255)/256, 256>>>(w_Wx_f, p_wxH,            p_wxL,            EDIM, EKP, HD3);
    conv_splitB_kernel<<<(EKP*HD3 + 255)/256, 256>>>(w_Wx_b, p_wxH + EKP*HD3,  p_wxL + EKP*HD3,  EDIM, EKP, HD3);
    conv_splitA_kernel<<<(HD2*HD2 + 255)/256, 256>>>(w_lin_W, p_linH, p_linL, HD2, HD2, (long long)HD2*HD2);
    conv_splitA_kernel<<<(HD2*HD3 + 255)/256, 256>>>(s_Wx_f, p_swxH,           p_swxL,           HD3, HD3, (long long)HD2*HD3);
    conv_splitA_kernel<<<(HD2*HD3 + 255)/256, 256>>>(s_Wx_b, p_swxH + HD2*HD3, p_swxL + HD2*HD3, HD3, HD3, (long long)HD2*HD3);
    conv_splitA_kernel<<<(HD2*HD2 + 255)/256, 256>>>(s_lin_W, p_slinH, p_slinL, HD2, HD2, (long long)HD2*HD2);
    // 1. word input gates (embedding gather fused, all-bf16 mainloop)
    mma_gemm_bf16_kernel<false><<<dim3(MWORD/128, 24), 256>>>(
        p_embH, p_embL, tokens, EKP, p_wxH, p_wxL, w_bx_f, w_bx_b, nullptr, p_xg, MWORD, 12);
    // 2. word BiGRU scan (writes fp32 h + bf16-split h)
    gru_scan_kernel<TW, 8><<<(NWSEQ/8)*2, 256>>>(
        p_xg, p_h, p_hbH, p_hbL, p_whp, w_bh_f, w_bh_b, NWSEQ);
    // 3. word rep GEMM fused into scores
    mma_gemm_bf16_kernel<true><<<dim3(MWORD/128, 8), 256>>>(
        p_hbH, p_hbL, nullptr, HD2, p_linH, p_linL, w_lin_b, w_lin_b, w_ctx, p_xg, MWORD, 8);
    // 4. word attention epilogue -> sentence vectors (fp32) + bf16 split
    attn_epi_kernel<TW, false><<<NWSEQ, 256>>>(
        p_xg, p_h, p_sents, nullptr, nullptr, nullptr, MWORD);
    conv_splitA_kernel<<<(MSENT*HD2 + 255)/256, 256>>>(p_sents, p_sbH, p_sbL, HD2, HD2, (long long)MSENT*HD2);
    // 5. sentence input gates
    mma_gemm_bf16_kernel<false><<<dim3(MSENT/128, 24), 256>>>(
        p_sbH, p_sbL, nullptr, HD2, p_swxH, p_swxL, s_bx_f, s_bx_b, nullptr, p_xg2, MSENT, 12);
    // 6. sentence BiGRU scan
    gru_scan_kernel<TSENT, 2><<<(NDOC/2)*2, 256>>>(
        p_xg2, p_h2, p_h2bH, p_h2bL, p_whp2, s_bh_f, s_bh_b, NDOC);
    // 7. sentence rep+score GEMM
    mma_gemm_bf16_kernel<true><<<dim3(MSENT/128, 8), 256>>>(
        p_h2bH, p_h2bL, nullptr, HD2, p_slinH, p_slinL, s_lin_b, s_lin_b, s_ctx, p_xg2, MSENT, 8);
    // 8. sentence attention + final classifier
    attn_epi_kernel<TSENT, true><<<NDOC, 256>>>(
        p_xg2, p_h2, nullptr, out_W, out_b, out, MSENT);
}

// round 11
// speedup vs baseline: 1.2641x; 1.1769x over previous
#include <cuda_runtime.h>
#include <cuda_bf16.h>
#include <cstdint>
#include <cstddef>

#define NWSEQ 1024
#define TW    64
#define MWORD (NWSEQ*TW)
#define NDOC  32
#define TSENT 32
#define MSENT (NDOC*TSENT)
#define HD2   512
#define HD3   768
#define EDIM  200
#define VMAX  50000
#define EKP   224

typedef unsigned long long ull;
typedef unsigned short u16;

// scratch
__device__ float g_xg [2ull*MWORD*HD3];     // word input gates; later partial scores
__device__ float g_xg2[2ull*MSENT*HD3];     // sentence input gates; later partial scores
__device__ float4 g_whp [2*256*256 + 1024];
__device__ float4 g_whp2[2*256*256 + 1024];
// bf16-split planes
__device__ __nv_bfloat16 g_embC_hi[(size_t)VMAX*EKP], g_embC_lo[(size_t)VMAX*EKP];
__device__ __nv_bfloat16 g_wxC_hi [2*EKP*HD3],  g_wxC_lo [2*EKP*HD3];
__device__ __nv_bfloat16 g_linC_hi[HD2*HD2],    g_linC_lo[HD2*HD2];
__device__ __nv_bfloat16 g_swxC_hi[2*HD2*HD3],  g_swxC_lo[2*HD2*HD3];
__device__ __nv_bfloat16 g_slinC_hi[HD2*HD2],   g_slinC_lo[HD2*HD2];
__device__ __nv_bfloat16 g_hb_hi[(size_t)MWORD*HD2], g_hb_lo[(size_t)MWORD*HD2];
__device__ __nv_bfloat16 g_sb_hi[(size_t)MSENT*HD2], g_sb_lo[(size_t)MSENT*HD2];
__device__ __nv_bfloat16 g_h2b_hi[(size_t)MSENT*HD2], g_h2b_lo[(size_t)MSENT*HD2];

__device__ __forceinline__ ull pk2(float lo, float hi){
    ull r; asm("mov.b64 %0, {%1,%2};" : "=l"(r) : "f"(lo), "f"(hi)); return r;
}
__device__ __forceinline__ float2 upk2(ull v){
    float2 f; asm("mov.b64 {%0,%1}, %2;" : "=f"(f.x), "=f"(f.y) : "l"(v)); return f;
}
__device__ __forceinline__ ull fma2(ull a, ull b, ull c){
    ull d; asm("fma.rn.f32x2 %0, %1, %2, %3;" : "=l"(d) : "l"(a), "l"(b), "l"(c)); return d;
}
__device__ __forceinline__ float fsig(float x){ return 1.0f/(1.0f + __expf(-x)); }
__device__ __forceinline__ float ftanh(float x){ return 1.0f - 2.0f/(__expf(2.0f*x) + 1.0f); }

__device__ __forceinline__ void ldsm4(uint32_t& r0, uint32_t& r1, uint32_t& r2, uint32_t& r3, uint32_t addr){
    asm volatile("ldmatrix.sync.aligned.m8n8.x4.shared.b16 {%0,%1,%2,%3}, [%4];"
        : "=r"(r0), "=r"(r1), "=r"(r2), "=r"(r3) : "r"(addr));
}
__device__ __forceinline__ void ldsm4t(uint32_t& r0, uint32_t& r1, uint32_t& r2, uint32_t& r3, uint32_t addr){
    asm volatile("ldmatrix.sync.aligned.m8n8.x4.trans.shared.b16 {%0,%1,%2,%3}, [%4];"
        : "=r"(r0), "=r"(r1), "=r"(r2), "=r"(r3) : "r"(addr));
}
__device__ __forceinline__ void mma16816(float* d, uint32_t a0, uint32_t a1, uint32_t a2, uint32_t a3,
                                         uint32_t b0, uint32_t b1){
    asm volatile("mma.sync.aligned.m16n8k16.row.col.f32.bf16.bf16.f32 "
        "{%0,%1,%2,%3}, {%4,%5,%6,%7}, {%8,%9}, {%0,%1,%2,%3};"
        : "+f"(d[0]), "+f"(d[1]), "+f"(d[2]), "+f"(d[3])
        : "r"(a0), "r"(a1), "r"(a2), "r"(a3), "r"(b0), "r"(b1));
}

// ---------------------------------------------------------------------------
// One-time converters
// ---------------------------------------------------------------------------
__global__ void conv_splitA_kernel(const float* __restrict__ src,
                                   __nv_bfloat16* __restrict__ hi, __nv_bfloat16* __restrict__ lo,
                                   int K, int KP, long long total){
    long long i = (long long)blockIdx.x * blockDim.x + threadIdx.x;
    if (i >= total) return;
    int col = (int)(i % KP);
    long long row = i / KP;
    float v = (col < K) ? src[row * K + col] : 0.f;
    __nv_bfloat16 h = __float2bfloat16_rn(v);
    hi[i] = h;
    lo[i] = __float2bfloat16_rn(v - __bfloat162float(h));
}
__global__ void conv_splitB_kernel(const float* __restrict__ src,
                                   __nv_bfloat16* __restrict__ hi, __nv_bfloat16* __restrict__ lo,
                                   int K, int KP, int N){
    long long i = (long long)blockIdx.x * blockDim.x + threadIdx.x;
    if (i >= (long long)KP * N) return;
    int n = (int)(i % N);
    int k = (int)(i / N);
    float v = (k < K) ? src[(size_t)k * N + n] : 0.f;
    __nv_bfloat16 h = __float2bfloat16_rn(v);
    hi[i] = h;
    lo[i] = __float2bfloat16_rn(v - __bfloat162float(h));
}

__global__ void repack_wh_kernel(const float* __restrict__ Whf,
                                 const float* __restrict__ Whb,
                                 float4* __restrict__ whp){
    int k = blockIdx.x, d = blockIdx.y, j = threadIdx.x;
    const float* Wh = d ? Whb : Whf;
    float4 v;
    v.x = Wh[(size_t)k*HD3 + j];
    v.y = Wh[(size_t)k*HD3 + 256 + j];
    v.z = Wh[(size_t)k*HD3 + 512 + j];
    v.w = 0.f;
    whp[((size_t)d*256 + k)*256 + j] = v;
}

// ---------------------------------------------------------------------------
// bf16-split tensor-core GEMM (unchanged from R10 — proven).
// ---------------------------------------------------------------------------
#define ASTR 40
#define BSTR 72
template<bool SCORE>
__global__ __launch_bounds__(256,2) void mma_gemm_bf16_kernel(
    const __nv_bfloat16* __restrict__ Ahi, const __nv_bfloat16* __restrict__ Alo,
    const int* __restrict__ gather, int KP,
    const __nv_bfloat16* __restrict__ Bhi, const __nv_bfloat16* __restrict__ Blo,
    const float* __restrict__ bf_, const float* __restrict__ bb_,
    const float* __restrict__ ctx,
    float* __restrict__ out, int M, int nyPerDir)
{
    __shared__ __align__(16) u16 sAhi[128*ASTR], sAlo[128*ASTR];
    __shared__ __align__(16) u16 sBhi[32*BSTR],  sBlo[32*BSTR];
    int tid = threadIdx.x;
    int w = tid >> 5, lane = tid & 31;
    int g = lane >> 2, t4 = lane & 3;
    int m0 = blockIdx.x * 128;
    int dir = blockIdx.y / nyPerDir;
    int jb  = blockIdx.y % nyPerDir;
    int j0  = jb * 64;
    int ldw = nyPerDir * 64;
    const __nv_bfloat16* Bh = Bhi + (size_t)dir * KP * ldw;
    const __nv_bfloat16* Bl = Blo + (size_t)dir * KP * ldw;
    const float* bias = dir ? bb_ : bf_;

    int arow = tid >> 1, ahalf = tid & 1;
    int ridx = m0 + arow;
    size_t aro = (size_t)(gather ? gather[ridx] : ridx) * KP + ahalf * 16;
    const __nv_bfloat16* aph = Ahi + aro;
    const __nv_bfloat16* apl = Alo + aro;
    int bkr = tid >> 3, bc0 = (tid & 7) * 8;
    size_t bo = (size_t)bkr * ldw + j0 + bc0;

    float acc[8][4];
#pragma unroll
    for (int n = 0; n < 8; n++){ acc[n][0]=acc[n][1]=acc[n][2]=acc[n][3]=0.f; }

    uint32_t sAhiB = (uint32_t)__cvta_generic_to_shared(sAhi);
    uint32_t sAloB = (uint32_t)__cvta_generic_to_shared(sAlo);
    uint32_t sBhiB = (uint32_t)__cvta_generic_to_shared(sBhi);
    uint32_t sBloB = (uint32_t)__cvta_generic_to_shared(sBlo);
    uint32_t aOff = ((w*16 + (lane & 15)) * ASTR + (lane >> 4) * 8) * 2;
    uint32_t bT = ((lane & 15) * BSTR + (lane >> 4) * 8) * 2;

    int nt = KP / 32;
    uint4 rah0, rah1, ral0, ral1, rbh, rbl;

    rah0 = *(const uint4*)(aph);     rah1 = *(const uint4*)(aph + 8);
    ral0 = *(const uint4*)(apl);     ral1 = *(const uint4*)(apl + 8);
    rbh  = *(const uint4*)(Bh + bo); rbl  = *(const uint4*)(Bl + bo);

    for (int t = 0; t < nt; t++) {
        __syncthreads();
        {
            int abase = arow * ASTR + ahalf * 16;
            *(uint4*)&sAhi[abase]     = rah0;
            *(uint4*)&sAhi[abase + 8] = rah1;
            *(uint4*)&sAlo[abase]     = ral0;
            *(uint4*)&sAlo[abase + 8] = ral1;
            int bbase = bkr * BSTR + bc0;
            *(uint4*)&sBhi[bbase] = rbh;
            *(uint4*)&sBlo[bbase] = rbl;
        }
        __syncthreads();
        if (t + 1 < nt) {
            int k0 = (t + 1) * 32;
            rah0 = *(const uint4*)(aph + k0);     rah1 = *(const uint4*)(aph + k0 + 8);
            ral0 = *(const uint4*)(apl + k0);     ral1 = *(const uint4*)(apl + k0 + 8);
            size_t b2 = bo + (size_t)k0 * ldw;
            rbh = *(const uint4*)(Bh + b2);       rbl = *(const uint4*)(Bl + b2);
        }
#pragma unroll
        for (int h = 0; h < 2; h++){
            uint32_t ah0,ah1,ah2,ah3, al0,al1,al2,al3;
            ldsm4(ah0,ah1,ah2,ah3, sAhiB + aOff + h*32);
            ldsm4(al0,al1,al2,al3, sAloB + aOff + h*32);
#pragma unroll
            for (int np = 0; np < 4; np++){
                uint32_t ba = bT + h*16*BSTR*2 + np*32;
                uint32_t bh0,bh1,bh2,bh3, bl0,bl1,bl2,bl3;
                ldsm4t(bh0,bh1,bh2,bh3, sBhiB + ba);
                ldsm4t(bl0,bl1,bl2,bl3, sBloB + ba);
                mma16816(acc[2*np],   ah0,ah1,ah2,ah3, bh0,bh1);
                mma16816(acc[2*np],   ah0,ah1,ah2,ah3, bl0,bl1);
                mma16816(acc[2*np],   al0,al1,al2,al3, bh0,bh1);
                mma16816(acc[2*np+1], ah0,ah1,ah2,ah3, bh2,bh3);
                mma16816(acc[2*np+1], ah0,ah1,ah2,ah3, bl2,bl3);
                mma16816(acc[2*np+1], al0,al1,al2,al3, bh2,bh3);
            }
        }
    }

    if (!SCORE) {
        float* od = out + (size_t)dir * M * ldw;
        int r0 = m0 + w*16 + g;
#pragma unroll
        for (int n = 0; n < 8; n++){
            int c = j0 + n*8 + t4*2;
            float b0 = __ldg(&bias[c]), b1 = __ldg(&bias[c+1]);
            float2 o0{acc[n][0] + b0, acc[n][1] + b1};
            float2 o1{acc[n][2] + b0, acc[n][3] + b1};
            *(float2*)&od[(size_t)r0 * ldw + c]       = o0;
            *(float2*)&od[(size_t)(r0+8) * ldw + c]   = o1;
        }
    } else {
        float s0 = 0.f, s1 = 0.f;
#pragma unroll
        for (int n = 0; n < 8; n++){
            int c = j0 + n*8 + t4*2;
            float b0 = __ldg(&bias[c]), b1 = __ldg(&bias[c+1]);
            float c0 = __ldg(&ctx[c]),  c1 = __ldg(&ctx[c+1]);
            s0 += ftanh(acc[n][0] + b0)*c0 + ftanh(acc[n][1] + b1)*c1;
            s1 += ftanh(acc[n][2] + b0)*c0 + ftanh(acc[n][3] + b1)*c1;
        }
        s0 += __shfl_xor_sync(0xffffffffu, s0, 1); s0 += __shfl_xor_sync(0xffffffffu, s0, 2);
        s1 += __shfl_xor_sync(0xffffffffu, s1, 1); s1 += __shfl_xor_sync(0xffffffffu, s1, 2);
        if (t4 == 0){
            int r0 = m0 + w*16 + g;
            out[(size_t)jb * M + r0]     = s0;
            out[(size_t)jb * M + r0 + 8] = s1;
        }
    }
}

// ---------------------------------------------------------------------------
// GRU scan (G=8 proven config). Changes vs R10:
//  - h pairs loaded as ulonglong2 (LDS.128) when G%4==0
//  - epilogue x-loads batched (all 24 issued before gate math)
//  - fp32 h output dropped; only bf16 hi/lo planes written
// ---------------------------------------------------------------------------
template<int T, int G>
__global__ __launch_bounds__(256,2) void gru_scan_kernel(
    const float* __restrict__ xg,
    __nv_bfloat16* __restrict__ hb_hi, __nv_bfloat16* __restrict__ hb_lo,
    const float4* __restrict__ whp,
    const float* __restrict__ bhf, const float* __restrict__ bhb, int NS)
{
    constexpr int P = G / 2;
    __shared__ __align__(16) float sh[2][256][G];
    int j = threadIdx.x;
    int gpd = NS / G;
    int d  = blockIdx.x / gpd;
    int n0 = (blockIdx.x % gpd) * G;
    const float* bh = d ? bhb : bhf;
    const float4* Wp = whp + (size_t)d * 256 * 256;
    const float* xgd = xg + (size_t)d * NS * T * HD3;
    float bhr = bh[j], bhz = bh[256 + j], bhn = bh[512 + j];
    float hprev[G];
#pragma unroll
    for (int gg = 0; gg < G; gg++){ hprev[gg] = 0.f; sh[0][j][gg] = 0.f; }
    __syncthreads();

    int cur = 0;
    for (int tt = 0; tt < T; tt++) {
        int t = d ? (T - 1 - tt) : tt;
        ull ar[P], az[P], an[P];
#pragma unroll
        for (int p = 0; p < P; p++){
            ar[p] = pk2(bhr, bhr); az[p] = pk2(bhz, bhz); an[p] = pk2(bhn, bhn);
        }
        float4 w = Wp[j];
#pragma unroll 8
        for (int k = 0; k < 256; k++) {
            float4 wnext = Wp[(size_t)(k + 1) * 256 + j];
            ull wr2 = pk2(w.x, w.x), wz2 = pk2(w.y, w.y), wn2 = pk2(w.z, w.z);
            if constexpr ((G & 3) == 0) {
#pragma unroll
                for (int q = 0; q < P/2; q++){
                    ulonglong2 hq = *(const ulonglong2*)&sh[cur][k][4*q];
                    ar[2*q]   = fma2(wr2, hq.x, ar[2*q]);
                    az[2*q]   = fma2(wz2, hq.x, az[2*q]);
                    an[2*q]   = fma2(wn2, hq.x, an[2*q]);
                    ar[2*q+1] = fma2(wr2, hq.y, ar[2*q+1]);
                    az[2*q+1] = fma2(wz2, hq.y, az[2*q+1]);
                    an[2*q+1] = fma2(wn2, hq.y, an[2*q+1]);
                }
            } else {
#pragma unroll
                for (int p = 0; p < P; p++){
                    ull h2 = *(const ull*)&sh[cur][k][2*p];
                    ar[p] = fma2(wr2, h2, ar[p]);
                    az[p] = fma2(wz2, h2, az[p]);
                    an[p] = fma2(wn2, h2, an[p]);
                }
            }
            w = wnext;
        }
        int nxt = cur ^ 1;
        // batched x-gate loads (issued together -> one latency exposure)
        float xr[G], xz[G], xn[G];
#pragma unroll
        for (int gg = 0; gg < G; gg++){
            const float* xp = xgd + ((size_t)(n0 + gg) * T + t) * HD3;
            xr[gg] = xp[j]; xz[gg] = xp[256 + j]; xn[gg] = xp[512 + j];
        }
        float hnew[G];
#pragma unroll
        for (int p = 0; p < P; p++){
            float2 fr = upk2(ar[p]), fz = upk2(az[p]), fn = upk2(an[p]);
#pragma unroll
            for (int e = 0; e < 2; e++){
                int gg = 2*p + e;
                float hr = e ? fr.y : fr.x, hz = e ? fz.y : fz.x, hn = e ? fn.y : fn.x;
                float r = fsig(xr[gg] + hr), z = fsig(xz[gg] + hz);
                float n = ftanh(xn[gg] + r * hn);
                hnew[gg] = (1.f - z) * n + z * hprev[gg];
            }
        }
#pragma unroll
        for (int gg = 0; gg < G; gg++){
            float hv = hnew[gg];
            hprev[gg] = hv;
            sh[nxt][j][gg] = hv;
            size_t off = ((size_t)(n0 + gg) * T + t) * HD2 + d * 256 + j;
            __nv_bfloat16 bhv = __float2bfloat16_rn(hv);
            hb_hi[off] = bhv;
            hb_lo[off] = __float2bfloat16_rn(hv - __bfloat162float(bhv));
        }
        cur = nxt;
        __syncthreads();
    }
}

// ---------------------------------------------------------------------------
// Attention epilogue: partial scores -> sparsemax -> weighted sum of h
// (h reconstructed from bf16 hi/lo planes). Non-FINAL writes bf16-split
// sentence vectors directly; FINAL does doc @ outW + outb.
// ---------------------------------------------------------------------------
template<int T, bool FINAL>
__global__ __launch_bounds__(256) void attn_epi_kernel(
    const float* __restrict__ part,
    const __nv_bfloat16* __restrict__ h_hi, const __nv_bfloat16* __restrict__ h_lo,
    __nv_bfloat16* __restrict__ outv_hi, __nv_bfloat16* __restrict__ outv_lo,
    const float* __restrict__ outW,
    const float* __restrict__ outb,
    float* __restrict__ outFinal,
    int Mtot)
{
    __shared__ float sScore[T], sX[T], sSrt[T], sAtt[T];
    __shared__ float sTau, sMax;
    __shared__ float sDoc[512];
    int tid = threadIdx.x;
    int n = blockIdx.x;
    size_t hbase = (size_t)n * T * HD2;

    if (tid < T) {
        float s = 0.f;
#pragma unroll
        for (int jb = 0; jb < 8; jb++) s += part[(size_t)jb * Mtot + n * T + tid];
        sScore[tid] = s;
    }
    __syncthreads();
    if (tid == 0) {
        float mx = sScore[0];
        for (int t = 1; t < T; t++) mx = fmaxf(mx, sScore[t]);
        sMax = mx;
    }
    __syncthreads();
    if (tid < T) {
        float x = sScore[tid] - sMax;
        sX[tid] = x;
        int rank = 0;
        for (int u = 0; u < T; u++){
            float xu = sScore[u] - sMax;
            if (xu > x || (xu == x && u < tid)) rank++;
        }
        sSrt[rank] = x;
    }
    __syncthreads();
    if (tid == 0) {
        float cs = -1.f; int supp = 0; float csAt = 0.f;
        for (int k = 0; k < T; k++){
            cs += sSrt[k];
            if ((float)(k + 1) * sSrt[k] > cs) { supp = k + 1; csAt = cs; }
        }
        sTau = csAt / (float)supp;
    }
    __syncthreads();
    if (tid < T) sAtt[tid] = fmaxf(sX[tid] - sTau, 0.f);
    __syncthreads();
    {
        int jj = tid * 2;
        float ax = 0.f, ay = 0.f;
#pragma unroll 8
        for (int t = 0; t < T; t++){
            size_t off = hbase + (size_t)t * HD2 + jj;
            uint32_t ph = *(const uint32_t*)&h_hi[off];
            uint32_t pl = *(const uint32_t*)&h_lo[off];
            __nv_bfloat162 bh = *(__nv_bfloat162*)&ph;
            __nv_bfloat162 bl = *(__nv_bfloat162*)&pl;
            float hx = __bfloat162float(bh.x) + __bfloat162float(bl.x);
            float hy = __bfloat162float(bh.y) + __bfloat162float(bl.y);
            float a = sAtt[t];
            ax += a * hx; ay += a * hy;
        }
        if (FINAL){ sDoc[jj] = ax; sDoc[jj + 1] = ay; }
        else {
            size_t o = (size_t)n * HD2 + jj;
            __nv_bfloat16 hx = __float2bfloat16_rn(ax);
            __nv_bfloat16 hy = __float2bfloat16_rn(ay);
            __nv_bfloat162 hp = __halves2bfloat162(hx, hy);
            __nv_bfloat162 lp = __halves2bfloat162(
                __float2bfloat16_rn(ax - __bfloat162float(hx)),
                __float2bfloat16_rn(ay - __bfloat162float(hy)));
            *(uint32_t*)&outv_hi[o] = *(uint32_t*)&hp;
            *(uint32_t*)&outv_lo[o] = *(uint32_t*)&lp;
        }
    }
    if (FINAL) {
        __syncthreads();
        if (tid < 10) {
            float s = outb[tid];
            for (int jj2 = 0; jj2 < 512; jj2++) s += sDoc[jj2] * outW[jj2 * 10 + tid];
            outFinal[n * 10 + tid] = s;
        }
    }
}

extern "C" void kernel_launch(void* const* d_in, const int* in_sizes, int n_in,
                              void* d_out, int out_size) {
    const int*   tokens  = (const int*)  d_in[0];
    const float* emb     = (const float*)d_in[1];
    const float* w_Wx_f  = (const float*)d_in[2];
    const float* w_Wh_f  = (const float*)d_in[3];
    const float* w_bx_f  = (const float*)d_in[4];
    const float* w_bh_f  = (const float*)d_in[5];
    const float* w_Wx_b  = (const float*)d_in[6];
    const float* w_Wh_b  = (const float*)d_in[7];
    const float* w_bx_b  = (const float*)d_in[8];
    const float* w_bh_b  = (const float*)d_in[9];
    const float* w_lin_W = (const float*)d_in[10];
    const float* w_lin_b = (const float*)d_in[11];
    const float* w_ctx   = (const float*)d_in[12];
    const float* s_Wx_f  = (const float*)d_in[13];
    const float* s_Wh_f  = (const float*)d_in[14];
    const float* s_bx_f  = (const float*)d_in[15];
    const float* s_bh_f  = (const float*)d_in[16];
    const float* s_Wx_b  = (const float*)d_in[17];
    const float* s_Wh_b  = (const float*)d_in[18];
    const float* s_bx_b  = (const float*)d_in[19];
    const float* s_bh_b  = (const float*)d_in[20];
    const float* s_lin_W = (const float*)d_in[21];
    const float* s_lin_b = (const float*)d_in[22];
    const float* s_ctx   = (const float*)d_in[23];
    const float* out_W   = (const float*)d_in[24];
    const float* out_b   = (const float*)d_in[25];
    float* out = (float*)d_out;

    int V = in_sizes[1] / EDIM;

    float *p_xg, *p_xg2;
    float4 *p_whp, *p_whp2;
    __nv_bfloat16 *p_embH, *p_embL, *p_wxH, *p_wxL, *p_linH, *p_linL;
    __nv_bfloat16 *p_swxH, *p_swxL, *p_slinH, *p_slinL;
    __nv_bfloat16 *p_hbH, *p_hbL, *p_sbH, *p_sbL, *p_h2bH, *p_h2bL;
    cudaGetSymbolAddress((void**)&p_xg,   g_xg);
    cudaGetSymbolAddress((void**)&p_xg2,  g_xg2);
    cudaGetSymbolAddress((void**)&p_whp,  g_whp);
    cudaGetSymbolAddress((void**)&p_whp2, g_whp2);
    cudaGetSymbolAddress((void**)&p_embH, g_embC_hi);  cudaGetSymbolAddress((void**)&p_embL, g_embC_lo);
    cudaGetSymbolAddress((void**)&p_wxH,  g_wxC_hi);   cudaGetSymbolAddress((void**)&p_wxL,  g_wxC_lo);
    cudaGetSymbolAddress((void**)&p_linH, g_linC_hi);  cudaGetSymbolAddress((void**)&p_linL, g_linC_lo);
    cudaGetSymbolAddress((void**)&p_swxH, g_swxC_hi);  cudaGetSymbolAddress((void**)&p_swxL, g_swxC_lo);
    cudaGetSymbolAddress((void**)&p_slinH,g_slinC_hi); cudaGetSymbolAddress((void**)&p_slinL,g_slinC_lo);
    cudaGetSymbolAddress((void**)&p_hbH,  g_hb_hi);    cudaGetSymbolAddress((void**)&p_hbL,  g_hb_lo);
    cudaGetSymbolAddress((void**)&p_sbH,  g_sb_hi);    cudaGetSymbolAddress((void**)&p_sbL,  g_sb_lo);
    cudaGetSymbolAddress((void**)&p_h2bH, g_h2b_hi);   cudaGetSymbolAddress((void**)&p_h2bL, g_h2b_lo);

    // 0. one-time conversions / repacks
    repack_wh_kernel<<<dim3(256,2), 256>>>(w_Wh_f, w_Wh_b, p_whp);
    repack_wh_kernel<<<dim3(256,2), 256>>>(s_Wh_f, s_Wh_b, p_whp2);
    {
        long long tot = (long long)V * EKP;
        conv_splitA_kernel<<<(unsigned)((tot + 255) / 256), 256>>>(emb, p_embH, p_embL, EDIM, EKP, tot);
    }
    conv_splitB_kernel<<<(EKP*HD3 + 255)/256, 256>>>(w_Wx_f, p_wxH,            p_wxL,            EDIM, EKP, HD3);
    conv_splitB_kernel<<<(EKP*HD3 + 255)/256, 256>>>(w_Wx_b, p_wxH + EKP*HD3,  p_wxL + EKP*HD3,  EDIM, EKP, HD3);
    conv_splitA_kernel<<<(HD2*HD2 + 255)/256, 256>>>(w_lin_W, p_linH, p_linL, HD2, HD2, (long long)HD2*HD2);
    conv_splitA_kernel<<<(HD2*HD3 + 255)/256, 256>>>(s_Wx_f, p_swxH,           p_swxL,           HD3, HD3, (long long)HD2*HD3);
    conv_splitA_kernel<<<(HD2*HD3 + 255)/256, 256>>>(s_Wx_b, p_swxH + HD2*HD3, p_swxL + HD2*HD3, HD3, HD3, (long long)HD2*HD3);
    conv_splitA_kernel<<<(HD2*HD2 + 255)/256, 256>>>(s_lin_W, p_slinH, p_slinL, HD2, HD2, (long long)HD2*HD2);
    // 1. word input gates (embedding gather fused)
    mma_gemm_bf16_kernel<false><<<dim3(MWORD/128, 24), 256>>>(
        p_embH, p_embL, tokens, EKP, p_wxH, p_wxL, w_bx_f, w_bx_b, nullptr, p_xg, MWORD, 12);
    // 2. word BiGRU scan (bf16-split h output only)
    gru_scan_kernel<TW, 8><<<(NWSEQ/8)*2, 256>>>(
        p_xg, p_hbH, p_hbL, p_whp, w_bh_f, w_bh_b, NWSEQ);
    // 3. word rep GEMM fused into scores (partials into g_xg)
    mma_gemm_bf16_kernel<true><<<dim3(MWORD/128, 8), 256>>>(
        p_hbH, p_hbL, nullptr, HD2, p_linH, p_linL, w_lin_b, w_lin_b, w_ctx, p_xg, MWORD, 8);
    // 4. word attention epilogue -> sentence vectors (bf16-split direct)
    attn_epi_kernel<TW, false><<<NWSEQ, 256>>>(
        p_xg, p_hbH, p_hbL, p_sbH, p_sbL, nullptr, nullptr, nullptr, MWORD);
    // 5. sentence input gates
    mma_gemm_bf16_kernel<false><<<dim3(MSENT/128, 24), 256>>>(
        p_sbH, p_sbL, nullptr, HD2, p_swxH, p_swxL, s_bx_f, s_bx_b, nullptr, p_xg2, MSENT, 12);
    // 6. sentence BiGRU scan
    gru_scan_kernel<TSENT, 2><<<(NDOC/2)*2, 256>>>(
        p_xg2, p_h2bH, p_h2bL, p_whp2, s_bh_f, s_bh_b, NDOC);
    // 7. sentence rep+score GEMM (partials into g_xg2)
    mma_gemm_bf16_kernel<true><<<dim3(MSENT/128, 8), 256>>>(
        p_h2bH, p_h2bL, nullptr, HD2, p_slinH, p_slinL, s_lin_b, s_lin_b, s_ctx, p_xg2, MSENT, 8);
    // 8. sentence attention + final classifier
    attn_epi_kernel<TSENT, true><<<NDOC, 256>>>(
        p_xg2, p_h2bH, p_h2bL, nullptr, nullptr, out_W, out_b, out, MSENT);
}

// round 13
// speedup vs baseline: 1.3705x; 1.0842x over previous
#include <cuda_runtime.h>
#include <cuda_bf16.h>
#include <cstdint>
#include <cstddef>

#define NWSEQ 1024
#define TW    64
#define MWORD (NWSEQ*TW)
#define NDOC  32
#define TSENT 32
#define MSENT (NDOC*TSENT)
#define HD2   512
#define HD3   768
#define EDIM  200
#define VMAX  50000
#define EKP   224

typedef unsigned long long ull;
typedef unsigned short u16;
typedef __nv_bfloat16 bf16;

// scratch
__device__ float g_xg [2ull*MWORD*HD3];     // word input gates; later partial scores
__device__ float g_xg2[2ull*MSENT*HD3];
__device__ float4 g_whp [2*256*256 + 1024];
__device__ float4 g_whp2[2*256*256 + 1024];
// bf16-split planes (A row-major [row][KP]; weights row-major [KP][N])
__device__ bf16 g_embC_hi[(size_t)VMAX*EKP], g_embC_lo[(size_t)VMAX*EKP];
__device__ bf16 g_wxC_hi [2*EKP*HD3],  g_wxC_lo [2*EKP*HD3];
__device__ bf16 g_linC_hi[HD2*HD2],    g_linC_lo[HD2*HD2];
__device__ bf16 g_swxC_hi[2*HD2*HD3],  g_swxC_lo[2*HD2*HD3];
__device__ bf16 g_slinC_hi[HD2*HD2],   g_slinC_lo[HD2*HD2];
__device__ bf16 g_hb_hi[(size_t)MWORD*HD2], g_hb_lo[(size_t)MWORD*HD2];
__device__ bf16 g_sb_hi[(size_t)MSENT*HD2], g_sb_lo[(size_t)MSENT*HD2];
__device__ bf16 g_h2b_hi[(size_t)MSENT*HD2], g_h2b_lo[(size_t)MSENT*HD2];

__device__ __forceinline__ ull pk2(float lo, float hi){
    ull r; asm("mov.b64 %0, {%1,%2};" : "=l"(r) : "f"(lo), "f"(hi)); return r;
}
__device__ __forceinline__ float2 upk2(ull v){
    float2 f; asm("mov.b64 {%0,%1}, %2;" : "=f"(f.x), "=f"(f.y) : "l"(v)); return f;
}
__device__ __forceinline__ ull fma2(ull a, ull b, ull c){
    ull d; asm("fma.rn.f32x2 %0, %1, %2, %3;" : "=l"(d) : "l"(a), "l"(b), "l"(c)); return d;
}
__device__ __forceinline__ float fsig(float x){ return 1.0f/(1.0f + __expf(-x)); }
__device__ __forceinline__ float ftanh(float x){ return 1.0f - 2.0f/(__expf(2.0f*x) + 1.0f); }

__device__ __forceinline__ void ldsm4(uint32_t& r0, uint32_t& r1, uint32_t& r2, uint32_t& r3, uint32_t addr){
    asm volatile("ldmatrix.sync.aligned.m8n8.x4.shared.b16 {%0,%1,%2,%3}, [%4];"
        : "=r"(r0), "=r"(r1), "=r"(r2), "=r"(r3) : "r"(addr));
}
__device__ __forceinline__ void ldsm4t(uint32_t& r0, uint32_t& r1, uint32_t& r2, uint32_t& r3, uint32_t addr){
    asm volatile("ldmatrix.sync.aligned.m8n8.x4.trans.shared.b16 {%0,%1,%2,%3}, [%4];"
        : "=r"(r0), "=r"(r1), "=r"(r2), "=r"(r3) : "r"(addr));
}
__device__ __forceinline__ void mma16816(float* d, uint32_t a0, uint32_t a1, uint32_t a2, uint32_t a3,
                                         uint32_t b0, uint32_t b1){
    asm volatile("mma.sync.aligned.m16n8k16.row.col.f32.bf16.bf16.f32 "
        "{%0,%1,%2,%3}, {%4,%5,%6,%7}, {%8,%9}, {%0,%1,%2,%3};"
        : "+f"(d[0]), "+f"(d[1]), "+f"(d[2]), "+f"(d[3])
        : "r"(a0), "r"(a1), "r"(a2), "r"(a3), "r"(b0), "r"(b1));
}
__device__ __forceinline__ void cpa16(uint32_t dst, const void* src){
    asm volatile("cp.async.cg.shared.global [%0], [%1], 16;" :: "r"(dst), "l"(src) : "memory");
}
#define CPA_COMMIT() asm volatile("cp.async.commit_group;" ::: "memory")
#define CPA_WAIT1()  asm volatile("cp.async.wait_group 1;" ::: "memory")
#define CPA_WAIT0()  asm volatile("cp.async.wait_group 0;" ::: "memory")

// ---------------------------------------------------------------------------
// One-time converters (R11 proven)
// ---------------------------------------------------------------------------
__global__ void conv_splitA_kernel(const float* __restrict__ src,
                                   bf16* __restrict__ hi, bf16* __restrict__ lo,
                                   int K, int KP, long long total){
    long long i = (long long)blockIdx.x * blockDim.x + threadIdx.x;
    if (i >= total) return;
    int col = (int)(i % KP);
    long long row = i / KP;
    float v = (col < K) ? src[row * K + col] : 0.f;
    bf16 h = __float2bfloat16_rn(v);
    hi[i] = h;
    lo[i] = __float2bfloat16_rn(v - __bfloat162float(h));
}
__global__ void conv_splitB_kernel(const float* __restrict__ src,
                                   bf16* __restrict__ hi, bf16* __restrict__ lo,
                                   int K, int KP, int N){
    long long i = (long long)blockIdx.x * blockDim.x + threadIdx.x;
    if (i >= (long long)KP * N) return;
    int n = (int)(i % N);
    int k = (int)(i / N);
    float v = (k < K) ? src[(size_t)k * N + n] : 0.f;
    bf16 h = __float2bfloat16_rn(v);
    hi[i] = h;
    lo[i] = __float2bfloat16_rn(v - __bfloat162float(h));
}
__global__ void repack_wh_kernel(const float* __restrict__ Whf,
                                 const float* __restrict__ Whb,
                                 float4* __restrict__ whp){
    int k = blockIdx.x, d = blockIdx.y, j = threadIdx.x;
    const float* Wh = d ? Whb : Whf;
    float4 v;
    v.x = Wh[(size_t)k*HD3 + j];
    v.y = Wh[(size_t)k*HD3 + 256 + j];
    v.z = Wh[(size_t)k*HD3 + 512 + j];
    v.w = 0.f;
    whp[((size_t)d*256 + k)*256 + j] = v;
}

// ---------------------------------------------------------------------------
// bf16-split mma.sync GEMM v2. Block tile 128(M) x 128(N), k-tile 32.
// 8 warps as 4(m-groups of 32 rows) x 2(n-groups of 64 cols); each warp:
// 2 m16-tiles x 8 n8-tiles -> per k32-tile: 24 LDSM vs 96 HMMA.
// cp.async 2-stage double buffer (dynamic smem), no register prefetch.
//  SCORE=0: out[dir][m][j] = A[row(m)] @ B_dir + bias_dir  (ldw = nyPerDir*128)
//  SCORE=1: out[(jb*2+ng)*M + m] = sum over this warp's 64 cols of tanh(..)*ctx
// grid = (M/128, (SCORE?1:2)*nyPerDir)
// ---------------------------------------------------------------------------
#define ASTR 40     // u16 per A smem row (32 + 8 pad)
#define BSTR 136    // u16 per B smem row (128 + 8 pad)
#define OFF_AHI 0
#define OFF_ALO 10240
#define OFF_BHI 20480
#define OFF_BLO 29184
#define BUFSZ   37888
#define GSMEM   (2*BUFSZ)
template<bool SCORE>
__global__ __launch_bounds__(256,2) void mma2_kernel(
    const bf16* __restrict__ Ahi, const bf16* __restrict__ Alo,
    const int* __restrict__ gather, int KP,
    const bf16* __restrict__ Bhi, const bf16* __restrict__ Blo,
    const float* __restrict__ bf_, const float* __restrict__ bb_,
    const float* __restrict__ ctx,
    float* __restrict__ out, int M, int nyPerDir)
{
    extern __shared__ __align__(16) char dsm[];
    uint32_t sb;
    asm("{ .reg .u64 t; cvta.to.shared.u64 t, %1; cvt.u32.u64 %0, t; }" : "=r"(sb) : "l"(dsm));
    int tid = threadIdx.x;
    int w = tid >> 5, lane = tid & 31;
    int g = lane >> 2, t4 = lane & 3;
    int mg = w & 3, ng = w >> 2;
    int m0 = blockIdx.x * 128;
    int dir = blockIdx.y / nyPerDir;
    int jb  = blockIdx.y % nyPerDir;
    int j0  = jb * 128;
    int ldw = nyPerDir * 128;
    const bf16* Bh = Bhi + (size_t)dir * KP * ldw;
    const bf16* Bl = Blo + (size_t)dir * KP * ldw;
    const float* bias = dir ? bb_ : bf_;

    // loaders: A 2 thr/row x 16 elems; B 8 thr/row x 16 elems
    int arow = tid >> 1, ahalf = tid & 1;
    size_t arbase = (size_t)(gather ? gather[m0 + arow] : (m0 + arow)) * KP + ahalf * 16;
    uint32_t adst = (uint32_t)(arow * ASTR + ahalf * 16) * 2;
    int bkr = tid >> 3, bc0 = (tid & 7) * 16;
    size_t bo = (size_t)bkr * ldw + j0 + bc0;
    uint32_t bdst = (uint32_t)(bkr * BSTR + bc0) * 2;

    float acc[2][8][4];
#pragma unroll
    for (int mt = 0; mt < 2; mt++)
#pragma unroll
        for (int n = 0; n < 8; n++){ acc[mt][n][0]=acc[mt][n][1]=acc[mt][n][2]=acc[mt][n][3]=0.f; }

    uint32_t aOff0 = ((mg*32 + (lane & 15)) * ASTR + (lane >> 4) * 8) * 2;         // mt=0
    uint32_t aOff1 = ((mg*32 + 16 + (lane & 15)) * ASTR + (lane >> 4) * 8) * 2;    // mt=1
    uint32_t bT = ((lane & 15) * BSTR + (lane >> 4) * 8) * 2 + ng * 128;

    int nt = KP / 32;

#define ISSUE_TILE(BUFB, K0) do { \
    const bf16* _pa = Ahi + arbase + (K0); \
    const bf16* _pl = Alo + arbase + (K0); \
    cpa16((BUFB) + OFF_AHI + adst,      _pa); \
    cpa16((BUFB) + OFF_AHI + adst + 16, _pa + 8); \
    cpa16((BUFB) + OFF_ALO + adst,      _pl); \
    cpa16((BUFB) + OFF_ALO + adst + 16, _pl + 8); \
    const bf16* _pbh = Bh + bo + (size_t)(K0) * ldw; \
    const bf16* _pbl = Bl + bo + (size_t)(K0) * ldw; \
    cpa16((BUFB) + OFF_BHI + bdst,      _pbh); \
    cpa16((BUFB) + OFF_BHI + bdst + 16, _pbh + 8); \
    cpa16((BUFB) + OFF_BLO + bdst,      _pbl); \
    cpa16((BUFB) + OFF_BLO + bdst + 16, _pbl + 8); \
} while(0)

    ISSUE_TILE(sb, 0); CPA_COMMIT();
    if (nt > 1){ ISSUE_TILE(sb + BUFSZ, 32); CPA_COMMIT(); }

    for (int t = 0; t < nt; t++){
        if (t + 1 < nt) { CPA_WAIT1(); } else { CPA_WAIT0(); }
        __syncthreads();
        uint32_t bufb = sb + (t & 1) * BUFSZ;
#pragma unroll
        for (int h = 0; h < 2; h++){
            uint32_t a0h0,a0h1,a0h2,a0h3, a0l0,a0l1,a0l2,a0l3;
            uint32_t a1h0,a1h1,a1h2,a1h3, a1l0,a1l1,a1l2,a1l3;
            ldsm4(a0h0,a0h1,a0h2,a0h3, bufb + OFF_AHI + aOff0 + h*32);
            ldsm4(a0l0,a0l1,a0l2,a0l3, bufb + OFF_ALO + aOff0 + h*32);
            ldsm4(a1h0,a1h1,a1h2,a1h3, bufb + OFF_AHI + aOff1 + h*32);
            ldsm4(a1l0,a1l1,a1l2,a1l3, bufb + OFF_ALO + aOff1 + h*32);
#pragma unroll
            for (int np = 0; np < 4; np++){
                uint32_t ba = bT + h*16*BSTR*2 + np*32;
                uint32_t bh0,bh1,bh2,bh3, bl0,bl1,bl2,bl3;
                ldsm4t(bh0,bh1,bh2,bh3, bufb + OFF_BHI + ba);
                ldsm4t(bl0,bl1,bl2,bl3, bufb + OFF_BLO + ba);
                mma16816(acc[0][2*np],   a0h0,a0h1,a0h2,a0h3, bh0,bh1);
                mma16816(acc[0][2*np],   a0h0,a0h1,a0h2,a0h3, bl0,bl1);
                mma16816(acc[0][2*np],   a0l0,a0l1,a0l2,a0l3, bh0,bh1);
                mma16816(acc[0][2*np+1], a0h0,a0h1,a0h2,a0h3, bh2,bh3);
                mma16816(acc[0][2*np+1], a0h0,a0h1,a0h2,a0h3, bl2,bl3);
                mma16816(acc[0][2*np+1], a0l0,a0l1,a0l2,a0l3, bh2,bh3);
                mma16816(acc[1][2*np],   a1h0,a1h1,a1h2,a1h3, bh0,bh1);
                mma16816(acc[1][2*np],   a1h0,a1h1,a1h2,a1h3, bl0,bl1);
                mma16816(acc[1][2*np],   a1l0,a1l1,a1l2,a1l3, bh0,bh1);
                mma16816(acc[1][2*np+1], a1h0,a1h1,a1h2,a1h3, bh2,bh3);
                mma16816(acc[1][2*np+1], a1h0,a1h1,a1h2,a1h3, bl2,bl3);
                mma16816(acc[1][2*np+1], a1l0,a1l1,a1l2,a1l3, bh2,bh3);
            }
        }
        __syncthreads();
        if (t + 2 < nt){ ISSUE_TILE(bufb, (t + 2) * 32); CPA_COMMIT(); }
    }
#undef ISSUE_TILE

    if (!SCORE) {
        float* od = out + (size_t)dir * M * ldw;
#pragma unroll
        for (int mt = 0; mt < 2; mt++){
            int r0 = m0 + mg*32 + mt*16 + g;
#pragma unroll
            for (int n = 0; n < 8; n++){
                int c = j0 + ng*64 + n*8 + t4*2;
                float b0 = __ldg(&bias[c]), b1 = __ldg(&bias[c+1]);
                float2 o0{acc[mt][n][0] + b0, acc[mt][n][1] + b1};
                float2 o1{acc[mt][n][2] + b0, acc[mt][n][3] + b1};
                *(float2*)&od[(size_t)r0 * ldw + c]     = o0;
                *(float2*)&od[(size_t)(r0+8) * ldw + c] = o1;
            }
        }
    } else {
#pragma unroll
        for (int mt = 0; mt < 2; mt++){
            float s0 = 0.f, s1 = 0.f;
#pragma unroll
            for (int n = 0; n < 8; n++){
                int c = j0 + ng*64 + n*8 + t4*2;
                float b0 = __ldg(&bias[c]), b1 = __ldg(&bias[c+1]);
                float c0 = __ldg(&ctx[c]),  c1 = __ldg(&ctx[c+1]);
                s0 += ftanh(acc[mt][n][0] + b0)*c0 + ftanh(acc[mt][n][1] + b1)*c1;
                s1 += ftanh(acc[mt][n][2] + b0)*c0 + ftanh(acc[mt][n][3] + b1)*c1;
            }
            s0 += __shfl_xor_sync(0xffffffffu, s0, 1); s0 += __shfl_xor_sync(0xffffffffu, s0, 2);
            s1 += __shfl_xor_sync(0xffffffffu, s1, 1); s1 += __shfl_xor_sync(0xffffffffu, s1, 2);
            if (t4 == 0){
                int r0 = m0 + mg*32 + mt*16 + g;
                int pslot = jb * 2 + ng;
                out[(size_t)pslot * M + r0]     = s0;
                out[(size_t)pslot * M + r0 + 8] = s1;
            }
        }
    }
}

// ---------------------------------------------------------------------------
// GRU scan (R11 proven, unchanged)
// ---------------------------------------------------------------------------
template<int T, int G>
__global__ __launch_bounds__(256,2) void gru_scan_kernel(
    const float* __restrict__ xg,
    bf16* __restrict__ hb_hi, bf16* __restrict__ hb_lo,
    const float4* __restrict__ whp,
    const float* __restrict__ bhf, const float* __restrict__ bhb, int NS)
{
    constexpr int P = G / 2;
    __shared__ __align__(16) float sh[2][256][G];
    int j = threadIdx.x;
    int gpd = NS / G;
    int d  = blockIdx.x / gpd;
    int n0 = (blockIdx.x % gpd) * G;
    const float* bh = d ? bhb : bhf;
    const float4* Wp = whp + (size_t)d * 256 * 256;
    const float* xgd = xg + (size_t)d * NS * T * HD3;
    float bhr = bh[j], bhz = bh[256 + j], bhn = bh[512 + j];
    float hprev[G];
#pragma unroll
    for (int gg = 0; gg < G; gg++){ hprev[gg] = 0.f; sh[0][j][gg] = 0.f; }
    __syncthreads();

    int cur = 0;
    for (int tt = 0; tt < T; tt++) {
        int t = d ? (T - 1 - tt) : tt;
        ull ar[P], az[P], an[P];
#pragma unroll
        for (int p = 0; p < P; p++){
            ar[p] = pk2(bhr, bhr); az[p] = pk2(bhz, bhz); an[p] = pk2(bhn, bhn);
        }
        float4 w = Wp[j];
#pragma unroll 8
        for (int k = 0; k < 256; k++) {
            float4 wnext = Wp[(size_t)(k + 1) * 256 + j];
            ull wr2 = pk2(w.x, w.x), wz2 = pk2(w.y, w.y), wn2 = pk2(w.z, w.z);
            if constexpr ((G & 3) == 0) {
#pragma unroll
                for (int q = 0; q < P/2; q++){
                    ulonglong2 hq = *(const ulonglong2*)&sh[cur][k][4*q];
                    ar[2*q]   = fma2(wr2, hq.x, ar[2*q]);
                    az[2*q]   = fma2(wz2, hq.x, az[2*q]);
                    an[2*q]   = fma2(wn2, hq.x, an[2*q]);
                    ar[2*q+1] = fma2(wr2, hq.y, ar[2*q+1]);
                    az[2*q+1] = fma2(wz2, hq.y, az[2*q+1]);
                    an[2*q+1] = fma2(wn2, hq.y, an[2*q+1]);
                }
            } else {
#pragma unroll
                for (int p = 0; p < P; p++){
                    ull h2 = *(const ull*)&sh[cur][k][2*p];
                    ar[p] = fma2(wr2, h2, ar[p]);
                    az[p] = fma2(wz2, h2, az[p]);
                    an[p] = fma2(wn2, h2, an[p]);
                }
            }
            w = wnext;
        }
        int nxt = cur ^ 1;
        float xr[G], xz[G], xn[G];
#pragma unroll
        for (int gg = 0; gg < G; gg++){
            const float* xp = xgd + ((size_t)(n0 + gg) * T + t) * HD3;
            xr[gg] = xp[j]; xz[gg] = xp[256 + j]; xn[gg] = xp[512 + j];
        }
        float hnew[G];
#pragma unroll
        for (int p = 0; p < P; p++){
            float2 fr = upk2(ar[p]), fz = upk2(az[p]), fn = upk2(an[p]);
#pragma unroll
            for (int e = 0; e < 2; e++){
                int gg = 2*p + e;
                float hr = e ? fr.y : fr.x, hz = e ? fz.y : fz.x, hn = e ? fn.y : fn.x;
                float r = fsig(xr[gg] + hr), z = fsig(xz[gg] + hz);
                float n = ftanh(xn[gg] + r * hn);
                hnew[gg] = (1.f - z) * n + z * hprev[gg];
            }
        }
#pragma unroll
        for (int gg = 0; gg < G; gg++){
            float hv = hnew[gg];
            hprev[gg] = hv;
            sh[nxt][j][gg] = hv;
            size_t off = ((size_t)(n0 + gg) * T + t) * HD2 + d * 256 + j;
            bf16 bhv = __float2bfloat16_rn(hv);
            hb_hi[off] = bhv;
            hb_lo[off] = __float2bfloat16_rn(hv - __bfloat162float(bhv));
        }
        cur = nxt;
        __syncthreads();
    }
}

// ---------------------------------------------------------------------------
// Attention epilogue (R11 proven, unchanged)
// ---------------------------------------------------------------------------
template<int T, bool FINAL>
__global__ __launch_bounds__(256) void attn_epi_kernel(
    const float* __restrict__ part,
    const bf16* __restrict__ h_hi, const bf16* __restrict__ h_lo,
    bf16* __restrict__ outv_hi, bf16* __restrict__ outv_lo,
    const float* __restrict__ outW,
    const float* __restrict__ outb,
    float* __restrict__ outFinal,
    int Mtot)
{
    __shared__ float sScore[T], sX[T], sSrt[T], sAtt[T];
    __shared__ float sTau, sMax;
    __shared__ float sDoc[512];
    int tid = threadIdx.x;
    int n = blockIdx.x;
    size_t hbase = (size_t)n * T * HD2;

    if (tid < T) {
        float s = 0.f;
#pragma unroll
        for (int jb = 0; jb < 8; jb++) s += part[(size_t)jb * Mtot + n * T + tid];
        sScore[tid] = s;
    }
    __syncthreads();
    if (tid == 0) {
        float mx = sScore[0];
        for (int t = 1; t < T; t++) mx = fmaxf(mx, sScore[t]);
        sMax = mx;
    }
    __syncthreads();
    if (tid < T) {
        float x = sScore[tid] - sMax;
        sX[tid] = x;
        int rank = 0;
        for (int u = 0; u < T; u++){
            float xu = sScore[u] - sMax;
            if (xu > x || (xu == x && u < tid)) rank++;
        }
        sSrt[rank] = x;
    }
    __syncthreads();
    if (tid == 0) {
        float cs = -1.f; int supp = 0; float csAt = 0.f;
        for (int k = 0; k < T; k++){
            cs += sSrt[k];
            if ((float)(k + 1) * sSrt[k] > cs) { supp = k + 1; csAt = cs; }
        }
        sTau = csAt / (float)supp;
    }
    __syncthreads();
    if (tid < T) sAtt[tid] = fmaxf(sX[tid] - sTau, 0.f);
    __syncthreads();
    {
        int jj = tid * 2;
        float ax = 0.f, ay = 0.f;
#pragma unroll 8
        for (int t = 0; t < T; t++){
            size_t off = hbase + (size_t)t * HD2 + jj;
            uint32_t ph = *(const uint32_t*)&h_hi[off];
            uint32_t pl = *(const uint32_t*)&h_lo[off];
            __nv_bfloat162 bh = *(__nv_bfloat162*)&ph;
            __nv_bfloat162 bl = *(__nv_bfloat162*)&pl;
            float hx = __bfloat162float(bh.x) + __bfloat162float(bl.x);
            float hy = __bfloat162float(bh.y) + __bfloat162float(bl.y);
            float a = sAtt[t];
            ax += a * hx; ay += a * hy;
        }
        if (FINAL){ sDoc[jj] = ax; sDoc[jj + 1] = ay; }
        else {
            size_t o = (size_t)n * HD2 + jj;
            bf16 hx = __float2bfloat16_rn(ax);
            bf16 hy = __float2bfloat16_rn(ay);
            __nv_bfloat162 hp = __halves2bfloat162(hx, hy);
            __nv_bfloat162 lp = __halves2bfloat162(
                __float2bfloat16_rn(ax - __bfloat162float(hx)),
                __float2bfloat16_rn(ay - __bfloat162float(hy)));
            *(uint32_t*)&outv_hi[o] = *(uint32_t*)&hp;
            *(uint32_t*)&outv_lo[o] = *(uint32_t*)&lp;
        }
    }
    if (FINAL) {
        __syncthreads();
        if (tid < 10) {
            float s = outb[tid];
            for (int jj2 = 0; jj2 < 512; jj2++) s += sDoc[jj2] * outW[jj2 * 10 + tid];
            outFinal[n * 10 + tid] = s;
        }
    }
}

extern "C" void kernel_launch(void* const* d_in, const int* in_sizes, int n_in,
                              void* d_out, int out_size) {
    const int*   tokens  = (const int*)  d_in[0];
    const float* emb     = (const float*)d_in[1];
    const float* w_Wx_f  = (const float*)d_in[2];
    const float* w_Wh_f  = (const float*)d_in[3];
    const float* w_bx_f  = (const float*)d_in[4];
    const float* w_bh_f  = (const float*)d_in[5];
    const float* w_Wx_b  = (const float*)d_in[6];
    const float* w_Wh_b  = (const float*)d_in[7];
    const float* w_bx_b  = (const float*)d_in[8];
    const float* w_bh_b  = (const float*)d_in[9];
    const float* w_lin_W = (const float*)d_in[10];
    const float* w_lin_b = (const float*)d_in[11];
    const float* w_ctx   = (const float*)d_in[12];
    const float* s_Wx_f  = (const float*)d_in[13];
    const float* s_Wh_f  = (const float*)d_in[14];
    const float* s_bx_f  = (const float*)d_in[15];
    const float* s_bh_f  = (const float*)d_in[16];
    const float* s_Wx_b  = (const float*)d_in[17];
    const float* s_Wh_b  = (const float*)d_in[18];
    const float* s_bx_b  = (const float*)d_in[19];
    const float* s_bh_b  = (const float*)d_in[20];
    const float* s_lin_W = (const float*)d_in[21];
    const float* s_lin_b = (const float*)d_in[22];
    const float* s_ctx   = (const float*)d_in[23];
    const float* out_W   = (const float*)d_in[24];
    const float* out_b   = (const float*)d_in[25];
    float* out = (float*)d_out;

    int V = in_sizes[1] / EDIM;

    float *p_xg, *p_xg2;
    float4 *p_whp, *p_whp2;
    bf16 *p_embH, *p_embL, *p_wxH, *p_wxL, *p_linH, *p_linL;
    bf16 *p_swxH, *p_swxL, *p_slinH, *p_slinL;
    bf16 *p_hbH, *p_hbL, *p_sbH, *p_sbL, *p_h2bH, *p_h2bL;
    cudaGetSymbolAddress((void**)&p_xg,   g_xg);
    cudaGetSymbolAddress((void**)&p_xg2,  g_xg2);
    cudaGetSymbolAddress((void**)&p_whp,  g_whp);
    cudaGetSymbolAddress((void**)&p_whp2, g_whp2);
    cudaGetSymbolAddress((void**)&p_embH, g_embC_hi);  cudaGetSymbolAddress((void**)&p_embL, g_embC_lo);
    cudaGetSymbolAddress((void**)&p_wxH,  g_wxC_hi);   cudaGetSymbolAddress((void**)&p_wxL,  g_wxC_lo);
    cudaGetSymbolAddress((void**)&p_linH, g_linC_hi);  cudaGetSymbolAddress((void**)&p_linL, g_linC_lo);
    cudaGetSymbolAddress((void**)&p_swxH, g_swxC_hi);  cudaGetSymbolAddress((void**)&p_swxL, g_swxC_lo);
    cudaGetSymbolAddress((void**)&p_slinH,g_slinC_hi); cudaGetSymbolAddress((void**)&p_slinL,g_slinC_lo);
    cudaGetSymbolAddress((void**)&p_hbH,  g_hb_hi);    cudaGetSymbolAddress((void**)&p_hbL,  g_hb_lo);
    cudaGetSymbolAddress((void**)&p_sbH,  g_sb_hi);    cudaGetSymbolAddress((void**)&p_sbL,  g_sb_lo);
    cudaGetSymbolAddress((void**)&p_h2bH, g_h2b_hi);   cudaGetSymbolAddress((void**)&p_h2bL, g_h2b_lo);

    cudaFuncSetAttribute(mma2_kernel<false>, cudaFuncAttributeMaxDynamicSharedMemorySize, GSMEM);
    cudaFuncSetAttribute(mma2_kernel<true>,  cudaFuncAttributeMaxDynamicSharedMemorySize, GSMEM);

    // 0. one-time conversions / repacks
    repack_wh_kernel<<<dim3(256,2), 256>>>(w_Wh_f, w_Wh_b, p_whp);
    repack_wh_kernel<<<dim3(256,2), 256>>>(s_Wh_f, s_Wh_b, p_whp2);
    {
        long long tot = (long long)V * EKP;
        conv_splitA_kernel<<<(unsigned)((tot + 255) / 256), 256>>>(emb, p_embH, p_embL, EDIM, EKP, tot);
    }
    conv_splitB_kernel<<<(EKP*HD3 + 255)/256, 256>>>(w_Wx_f, p_wxH,            p_wxL,            EDIM, EKP, HD3);
    conv_splitB_kernel<<<(EKP*HD3 + 255)/256, 256>>>(w_Wx_b, p_wxH + EKP*HD3,  p_wxL + EKP*HD3,  EDIM, EKP, HD3);
    conv_splitB_kernel<<<(HD2*HD2 + 255)/256, 256>>>(w_lin_W, p_linH, p_linL, HD2, HD2, HD2);
    conv_splitB_kernel<<<(HD2*HD3 + 255)/256, 256>>>(s_Wx_f, p_swxH,           p_swxL,           HD2, HD2, HD3);
    conv_splitB_kernel<<<(HD2*HD3 + 255)/256, 256>>>(s_Wx_b, p_swxH + HD2*HD3, p_swxL + HD2*HD3, HD2, HD2, HD3);
    conv_splitB_kernel<<<(HD2*HD2 + 255)/256, 256>>>(s_lin_W, p_slinH, p_slinL, HD2, HD2, HD2);
    // 1. word input gates (embedding gather fused)
    mma2_kernel<false><<<dim3(MWORD/128, 12), 256, GSMEM>>>(
        p_embH, p_embL, tokens, EKP, p_wxH, p_wxL, w_bx_f, w_bx_b, nullptr, p_xg, MWORD, 6);
    // 2. word BiGRU scan
    gru_scan_kernel<TW, 8><<<(NWSEQ/8)*2, 256>>>(
        p_xg, p_hbH, p_hbL, p_whp, w_bh_f, w_bh_b, NWSEQ);
    // 3. word rep GEMM fused into scores (partials into g_xg: 8 slots)
    mma2_kernel<true><<<dim3(MWORD/128, 4), 256, GSMEM>>>(
        p_hbH, p_hbL, nullptr, HD2, p_linH, p_linL, w_lin_b, w_lin_b, w_ctx, p_xg, MWORD, 4);
    // 4. word attention epilogue -> sentence vectors (bf16-split direct)
    attn_epi_kernel<TW, false><<<NWSEQ, 256>>>(
        p_xg, p_hbH, p_hbL, p_sbH, p_sbL, nullptr, nullptr, nullptr, MWORD);
    // 5. sentence input gates
    mma2_kernel<false><<<dim3(MSENT/128, 12), 256, GSMEM>>>(
        p_sbH, p_sbL, nullptr, HD2, p_swxH, p_swxL, s_bx_f, s_bx_b, nullptr, p_xg2, MSENT, 6);
    // 6. sentence BiGRU scan
    gru_scan_kernel<TSENT, 2><<<(NDOC/2)*2, 256>>>(
        p_xg2, p_h2bH, p_h2bL, p_whp2, s_bh_f, s_bh_b, NDOC);
    // 7. sentence rep+score GEMM (partials into g_xg2)
    mma2_kernel<true><<<dim3(MSENT/128, 4), 256, GSMEM>>>(
        p_h2bH, p_h2bL, nullptr, HD2, p_slinH, p_slinL, s_lin_b, s_lin_b, s_ctx, p_xg2, MSENT, 4);
    // 8. sentence attention + final classifier
    attn_epi_kernel<TSENT, true><<<NDOC, 256>>>(
        p_xg2, p_h2bH, p_h2bL, nullptr, nullptr, out_W, out_b, out, MSENT);
}

// round 14
// speedup vs baseline: 1.4169x; 1.0339x over previous
#include <cuda_runtime.h>
#include <cuda_bf16.h>
#include <cstdint>
#include <cstddef>

#define NWSEQ 1024
#define TW    64
#define MWORD (NWSEQ*TW)
#define NDOC  32
#define TSENT 32
#define MSENT (NDOC*TSENT)
#define HD2   512
#define HD3   768
#define EDIM  200
#define VMAX  50000
#define EKP   224

typedef unsigned long long ull;
typedef unsigned short u16;
typedef __nv_bfloat16 bf16;

// scratch
__device__ float g_xg [2ull*MWORD*HD3];     // word input gates; later partial scores
__device__ float g_xg2[2ull*MSENT*HD3];
__device__ float4 g_whp [2*256*256 + 1024];
__device__ float4 g_whp2[2*256*256 + 1024];
// bf16-split planes (A row-major [row][KP]; weights row-major [KP][N])
__device__ bf16 g_embC_hi[(size_t)VMAX*EKP], g_embC_lo[(size_t)VMAX*EKP];
__device__ bf16 g_wxC_hi [2*EKP*HD3],  g_wxC_lo [2*EKP*HD3];
__device__ bf16 g_linC_hi[HD2*HD2],    g_linC_lo[HD2*HD2];
__device__ bf16 g_swxC_hi[2*HD2*HD3],  g_swxC_lo[2*HD2*HD3];
__device__ bf16 g_slinC_hi[HD2*HD2],   g_slinC_lo[HD2*HD2];
__device__ bf16 g_hb_hi[(size_t)MWORD*HD2], g_hb_lo[(size_t)MWORD*HD2];
__device__ bf16 g_sb_hi[(size_t)MSENT*HD2], g_sb_lo[(size_t)MSENT*HD2];
__device__ bf16 g_h2b_hi[(size_t)MSENT*HD2], g_h2b_lo[(size_t)MSENT*HD2];

__device__ __forceinline__ ull pk2(float lo, float hi){
    ull r; asm("mov.b64 %0, {%1,%2};" : "=l"(r) : "f"(lo), "f"(hi)); return r;
}
__device__ __forceinline__ float2 upk2(ull v){
    float2 f; asm("mov.b64 {%0,%1}, %2;" : "=f"(f.x), "=f"(f.y) : "l"(v)); return f;
}
__device__ __forceinline__ ull fma2(ull a, ull b, ull c){
    ull d; asm("fma.rn.f32x2 %0, %1, %2, %3;" : "=l"(d) : "l"(a), "l"(b), "l"(c)); return d;
}
__device__ __forceinline__ float fsig(float x){ return 1.0f/(1.0f + __expf(-x)); }
__device__ __forceinline__ float ftanh(float x){ return 1.0f - 2.0f/(__expf(2.0f*x) + 1.0f); }

__device__ __forceinline__ void ldsm4(uint32_t& r0, uint32_t& r1, uint32_t& r2, uint32_t& r3, uint32_t addr){
    asm volatile("ldmatrix.sync.aligned.m8n8.x4.shared.b16 {%0,%1,%2,%3}, [%4];"
        : "=r"(r0), "=r"(r1), "=r"(r2), "=r"(r3) : "r"(addr));
}
__device__ __forceinline__ void ldsm4t(uint32_t& r0, uint32_t& r1, uint32_t& r2, uint32_t& r3, uint32_t addr){
    asm volatile("ldmatrix.sync.aligned.m8n8.x4.trans.shared.b16 {%0,%1,%2,%3}, [%4];"
        : "=r"(r0), "=r"(r1), "=r"(r2), "=r"(r3) : "r"(addr));
}
__device__ __forceinline__ void mma16816(float* d, uint32_t a0, uint32_t a1, uint32_t a2, uint32_t a3,
                                         uint32_t b0, uint32_t b1){
    asm volatile("mma.sync.aligned.m16n8k16.row.col.f32.bf16.bf16.f32 "
        "{%0,%1,%2,%3}, {%4,%5,%6,%7}, {%8,%9}, {%0,%1,%2,%3};"
        : "+f"(d[0]), "+f"(d[1]), "+f"(d[2]), "+f"(d[3])
        : "r"(a0), "r"(a1), "r"(a2), "r"(a3), "r"(b0), "r"(b1));
}
__device__ __forceinline__ void cpa16(uint32_t dst, const void* src){
    asm volatile("cp.async.cg.shared.global [%0], [%1], 16;" :: "r"(dst), "l"(src) : "memory");
}
#define CPA_COMMIT() asm volatile("cp.async.commit_group;" ::: "memory")
#define CPA_WAIT1()  asm volatile("cp.async.wait_group 1;" ::: "memory")
#define CPA_WAIT0()  asm volatile("cp.async.wait_group 0;" ::: "memory")

// ---------------------------------------------------------------------------
// One-time converters (proven)
// ---------------------------------------------------------------------------
__global__ void conv_splitA_kernel(const float* __restrict__ src,
                                   bf16* __restrict__ hi, bf16* __restrict__ lo,
                                   int K, int KP, long long total){
    long long i = (long long)blockIdx.x * blockDim.x + threadIdx.x;
    if (i >= total) return;
    int col = (int)(i % KP);
    long long row = i / KP;
    float v = (col < K) ? src[row * K + col] : 0.f;
    bf16 h = __float2bfloat16_rn(v);
    hi[i] = h;
    lo[i] = __float2bfloat16_rn(v - __bfloat162float(h));
}
__global__ void conv_splitB_kernel(const float* __restrict__ src,
                                   bf16* __restrict__ hi, bf16* __restrict__ lo,
                                   int K, int KP, int N){
    long long i = (long long)blockIdx.x * blockDim.x + threadIdx.x;
    if (i >= (long long)KP * N) return;
    int n = (int)(i % N);
    int k = (int)(i / N);
    float v = (k < K) ? src[(size_t)k * N + n] : 0.f;
    bf16 h = __float2bfloat16_rn(v);
    hi[i] = h;
    lo[i] = __float2bfloat16_rn(v - __bfloat162float(h));
}
__global__ void repack_wh_kernel(const float* __restrict__ Whf,
                                 const float* __restrict__ Whb,
                                 float4* __restrict__ whp){
    int k = blockIdx.x, d = blockIdx.y, j = threadIdx.x;
    const float* Wh = d ? Whb : Whf;
    float4 v;
    v.x = Wh[(size_t)k*HD3 + j];
    v.y = Wh[(size_t)k*HD3 + 256 + j];
    v.z = Wh[(size_t)k*HD3 + 512 + j];
    v.w = 0.f;
    whp[((size_t)d*256 + k)*256 + j] = v;
}

// ---------------------------------------------------------------------------
// bf16-split mma.sync GEMM v3. Block tile 128x128, k-tile 32, warps 4(m)x2(n).
// cp.async 3-stage ring -> ONE __syncthreads per k-tile:
//  iter t: wait(tile t) / sync / compute buf[t%3] / issue tile t+2 into buf[(t+2)%3].
//  buf[(t+2)%3] was last read at iter t-1, which every warp completed before
//  passing this iteration's sync -> no second barrier needed.
// ---------------------------------------------------------------------------
#define ASTR 40     // u16 per A smem row (32 + 8 pad)
#define BSTR 136    // u16 per B smem row (128 + 8 pad)
#define OFF_AHI 0
#define OFF_ALO 10240
#define OFF_BHI 20480
#define OFF_BLO 29184
#define BUFSZ   37888
#define GSMEM   (3*BUFSZ)
template<bool SCORE>
__global__ __launch_bounds__(256,2) void mma2_kernel(
    const bf16* __restrict__ Ahi, const bf16* __restrict__ Alo,
    const int* __restrict__ gather, int KP,
    const bf16* __restrict__ Bhi, const bf16* __restrict__ Blo,
    const float* __restrict__ bf_, const float* __restrict__ bb_,
    const float* __restrict__ ctx,
    float* __restrict__ out, int M, int nyPerDir)
{
    extern __shared__ __align__(16) char dsm[];
    uint32_t sb;
    asm("{ .reg .u64 t; cvta.to.shared.u64 t, %1; cvt.u32.u64 %0, t; }" : "=r"(sb) : "l"(dsm));
    int tid = threadIdx.x;
    int w = tid >> 5, lane = tid & 31;
    int g = lane >> 2, t4 = lane & 3;
    int mg = w & 3, ng = w >> 2;
    int m0 = blockIdx.x * 128;
    int dir = blockIdx.y / nyPerDir;
    int jb  = blockIdx.y % nyPerDir;
    int j0  = jb * 128;
    int ldw = nyPerDir * 128;
    const bf16* Bh = Bhi + (size_t)dir * KP * ldw;
    const bf16* Bl = Blo + (size_t)dir * KP * ldw;
    const float* bias = dir ? bb_ : bf_;

    int arow = tid >> 1, ahalf = tid & 1;
    size_t arbase = (size_t)(gather ? gather[m0 + arow] : (m0 + arow)) * KP + ahalf * 16;
    uint32_t adst = (uint32_t)(arow * ASTR + ahalf * 16) * 2;
    int bkr = tid >> 3, bc0 = (tid & 7) * 16;
    size_t bo = (size_t)bkr * ldw + j0 + bc0;
    uint32_t bdst = (uint32_t)(bkr * BSTR + bc0) * 2;

    float acc[2][8][4];
#pragma unroll
    for (int mt = 0; mt < 2; mt++)
#pragma unroll
        for (int n = 0; n < 8; n++){ acc[mt][n][0]=acc[mt][n][1]=acc[mt][n][2]=acc[mt][n][3]=0.f; }

    uint32_t aOff0 = ((mg*32 + (lane & 15)) * ASTR + (lane >> 4) * 8) * 2;
    uint32_t aOff1 = ((mg*32 + 16 + (lane & 15)) * ASTR + (lane >> 4) * 8) * 2;
    uint32_t bT = ((lane & 15) * BSTR + (lane >> 4) * 8) * 2 + ng * 128;

    int nt = KP / 32;

#define ISSUE_TILE(BUFB, K0) do { \
    const bf16* _pa = Ahi + arbase + (K0); \
    const bf16* _pl = Alo + arbase + (K0); \
    cpa16((BUFB) + OFF_AHI + adst,      _pa); \
    cpa16((BUFB) + OFF_AHI + adst + 16, _pa + 8); \
    cpa16((BUFB) + OFF_ALO + adst,      _pl); \
    cpa16((BUFB) + OFF_ALO + adst + 16, _pl + 8); \
    const bf16* _pbh = Bh + bo + (size_t)(K0) * ldw; \
    const bf16* _pbl = Bl + bo + (size_t)(K0) * ldw; \
    cpa16((BUFB) + OFF_BHI + bdst,      _pbh); \
    cpa16((BUFB) + OFF_BHI + bdst + 16, _pbh + 8); \
    cpa16((BUFB) + OFF_BLO + bdst,      _pbl); \
    cpa16((BUFB) + OFF_BLO + bdst + 16, _pbl + 8); \
} while(0)

    ISSUE_TILE(sb, 0); CPA_COMMIT();
    if (nt > 1){ ISSUE_TILE(sb + BUFSZ, 32); CPA_COMMIT(); }

    int bufIdx = 0;
    for (int t = 0; t < nt; t++){
        if (t + 1 < nt) { CPA_WAIT1(); } else { CPA_WAIT0(); }
        __syncthreads();
        uint32_t bufb = sb + bufIdx * BUFSZ;
#pragma unroll
        for (int h = 0; h < 2; h++){
            uint32_t a0h0,a0h1,a0h2,a0h3, a0l0,a0l1,a0l2,a0l3;
            uint32_t a1h0,a1h1,a1h2,a1h3, a1l0,a1l1,a1l2,a1l3;
            ldsm4(a0h0,a0h1,a0h2,a0h3, bufb + OFF_AHI + aOff0 + h*32);
            ldsm4(a0l0,a0l1,a0l2,a0l3, bufb + OFF_ALO + aOff0 + h*32);
            ldsm4(a1h0,a1h1,a1h2,a1h3, bufb + OFF_AHI + aOff1 + h*32);
            ldsm4(a1l0,a1l1,a1l2,a1l3, bufb + OFF_ALO + aOff1 + h*32);
#pragma unroll
            for (int np = 0; np < 4; np++){
                uint32_t ba = bT + h*16*BSTR*2 + np*32;
                uint32_t bh0,bh1,bh2,bh3, bl0,bl1,bl2,bl3;
                ldsm4t(bh0,bh1,bh2,bh3, bufb + OFF_BHI + ba);
                ldsm4t(bl0,bl1,bl2,bl3, bufb + OFF_BLO + ba);
                mma16816(acc[0][2*np],   a0h0,a0h1,a0h2,a0h3, bh0,bh1);
                mma16816(acc[0][2*np],   a0h0,a0h1,a0h2,a0h3, bl0,bl1);
                mma16816(acc[0][2*np],   a0l0,a0l1,a0l2,a0l3, bh0,bh1);
                mma16816(acc[0][2*np+1], a0h0,a0h1,a0h2,a0h3, bh2,bh3);
                mma16816(acc[0][2*np+1], a0h0,a0h1,a0h2,a0h3, bl2,bl3);
                mma16816(acc[0][2*np+1], a0l0,a0l1,a0l2,a0l3, bh2,bh3);
                mma16816(acc[1][2*np],   a1h0,a1h1,a1h2,a1h3, bh0,bh1);
                mma16816(acc[1][2*np],   a1h0,a1h1,a1h2,a1h3, bl0,bl1);
                mma16816(acc[1][2*np],   a1l0,a1l1,a1l2,a1l3, bh0,bh1);
                mma16816(acc[1][2*np+1], a1h0,a1h1,a1h2,a1h3, bh2,bh3);
                mma16816(acc[1][2*np+1], a1h0,a1h1,a1h2,a1h3, bl2,bl3);
                mma16816(acc[1][2*np+1], a1l0,a1l1,a1l2,a1l3, bh2,bh3);
            }
        }
        if (t + 2 < nt){
            int nb = bufIdx + 2; if (nb >= 3) nb -= 3;
            ISSUE_TILE(sb + nb * BUFSZ, (t + 2) * 32); CPA_COMMIT();
        }
        bufIdx = (bufIdx == 2) ? 0 : bufIdx + 1;
    }
#undef ISSUE_TILE

    if (!SCORE) {
        float* od = out + (size_t)dir * M * ldw;
#pragma unroll
        for (int mt = 0; mt < 2; mt++){
            int r0 = m0 + mg*32 + mt*16 + g;
#pragma unroll
            for (int n = 0; n < 8; n++){
                int c = j0 + ng*64 + n*8 + t4*2;
                float b0 = __ldg(&bias[c]), b1 = __ldg(&bias[c+1]);
                float2 o0{acc[mt][n][0] + b0, acc[mt][n][1] + b1};
                float2 o1{acc[mt][n][2] + b0, acc[mt][n][3] + b1};
                *(float2*)&od[(size_t)r0 * ldw + c]     = o0;
                *(float2*)&od[(size_t)(r0+8) * ldw + c] = o1;
            }
        }
    } else {
#pragma unroll
        for (int mt = 0; mt < 2; mt++){
            float s0 = 0.f, s1 = 0.f;
#pragma unroll
            for (int n = 0; n < 8; n++){
                int c = j0 + ng*64 + n*8 + t4*2;
                float b0 = __ldg(&bias[c]), b1 = __ldg(&bias[c+1]);
                float c0 = __ldg(&ctx[c]),  c1 = __ldg(&ctx[c+1]);
                s0 += ftanh(acc[mt][n][0] + b0)*c0 + ftanh(acc[mt][n][1] + b1)*c1;
                s1 += ftanh(acc[mt][n][2] + b0)*c0 + ftanh(acc[mt][n][3] + b1)*c1;
            }
            s0 += __shfl_xor_sync(0xffffffffu, s0, 1); s0 += __shfl_xor_sync(0xffffffffu, s0, 2);
            s1 += __shfl_xor_sync(0xffffffffu, s1, 1); s1 += __shfl_xor_sync(0xffffffffu, s1, 2);
            if (t4 == 0){
                int r0 = m0 + mg*32 + mt*16 + g;
                int pslot = jb * 2 + ng;
                out[(size_t)pslot * M + r0]     = s0;
                out[(size_t)pslot * M + r0 + 8] = s1;
            }
        }
    }
}

// ---------------------------------------------------------------------------
// GRU scan (proven, unchanged)
// ---------------------------------------------------------------------------
template<int T, int G>
__global__ __launch_bounds__(256,2) void gru_scan_kernel(
    const float* __restrict__ xg,
    bf16* __restrict__ hb_hi, bf16* __restrict__ hb_lo,
    const float4* __restrict__ whp,
    const float* __restrict__ bhf, const float* __restrict__ bhb, int NS)
{
    constexpr int P = G / 2;
    __shared__ __align__(16) float sh[2][256][G];
    int j = threadIdx.x;
    int gpd = NS / G;
    int d  = blockIdx.x / gpd;
    int n0 = (blockIdx.x % gpd) * G;
    const float* bh = d ? bhb : bhf;
    const float4* Wp = whp + (size_t)d * 256 * 256;
    const float* xgd = xg + (size_t)d * NS * T * HD3;
    float bhr = bh[j], bhz = bh[256 + j], bhn = bh[512 + j];
    float hprev[G];
#pragma unroll
    for (int gg = 0; gg < G; gg++){ hprev[gg] = 0.f; sh[0][j][gg] = 0.f; }
    __syncthreads();

    int cur = 0;
    for (int tt = 0; tt < T; tt++) {
        int t = d ? (T - 1 - tt) : tt;
        ull ar[P], az[P], an[P];
#pragma unroll
        for (int p = 0; p < P; p++){
            ar[p] = pk2(bhr, bhr); az[p] = pk2(bhz, bhz); an[p] = pk2(bhn, bhn);
        }
        float4 w = Wp[j];
#pragma unroll 8
        for (int k = 0; k < 256; k++) {
            float4 wnext = Wp[(size_t)(k + 1) * 256 + j];
            ull wr2 = pk2(w.x, w.x), wz2 = pk2(w.y, w.y), wn2 = pk2(w.z, w.z);
            if constexpr ((G & 3) == 0) {
#pragma unroll
                for (int q = 0; q < P/2; q++){
                    ulonglong2 hq = *(const ulonglong2*)&sh[cur][k][4*q];
                    ar[2*q]   = fma2(wr2, hq.x, ar[2*q]);
                    az[2*q]   = fma2(wz2, hq.x, az[2*q]);
                    an[2*q]   = fma2(wn2, hq.x, an[2*q]);
                    ar[2*q+1] = fma2(wr2, hq.y, ar[2*q+1]);
                    az[2*q+1] = fma2(wz2, hq.y, az[2*q+1]);
                    an[2*q+1] = fma2(wn2, hq.y, an[2*q+1]);
                }
            } else {
#pragma unroll
                for (int p = 0; p < P; p++){
                    ull h2 = *(const ull*)&sh[cur][k][2*p];
                    ar[p] = fma2(wr2, h2, ar[p]);
                    az[p] = fma2(wz2, h2, az[p]);
                    an[p] = fma2(wn2, h2, an[p]);
                }
            }
            w = wnext;
        }
        int nxt = cur ^ 1;
        float xr[G], xz[G], xn[G];
#pragma unroll
        for (int gg = 0; gg < G; gg++){
            const float* xp = xgd + ((size_t)(n0 + gg) * T + t) * HD3;
            xr[gg] = xp[j]; xz[gg] = xp[256 + j]; xn[gg] = xp[512 + j];
        }
        float hnew[G];
#pragma unroll
        for (int p = 0; p < P; p++){
            float2 fr = upk2(ar[p]), fz = upk2(az[p]), fn = upk2(an[p]);
#pragma unroll
            for (int e = 0; e < 2; e++){
                int gg = 2*p + e;
                float hr = e ? fr.y : fr.x, hz = e ? fz.y : fz.x, hn = e ? fn.y : fn.x;
                float r = fsig(xr[gg] + hr), z = fsig(xz[gg] + hz);
                float n = ftanh(xn[gg] + r * hn);
                hnew[gg] = (1.f - z) * n + z * hprev[gg];
            }
        }
#pragma unroll
        for (int gg = 0; gg < G; gg++){
            float hv = hnew[gg];
            hprev[gg] = hv;
            sh[nxt][j][gg] = hv;
            size_t off = ((size_t)(n0 + gg) * T + t) * HD2 + d * 256 + j;
            bf16 bhv = __float2bfloat16_rn(hv);
            hb_hi[off] = bhv;
            hb_lo[off] = __float2bfloat16_rn(hv - __bfloat162float(bhv));
        }
        cur = nxt;
        __syncthreads();
    }
}

// ---------------------------------------------------------------------------
// Attention epilogue (proven, unchanged)
// ---------------------------------------------------------------------------
template<int T, bool FINAL>
__global__ __launch_bounds__(256) void attn_epi_kernel(
    const float* __restrict__ part,
    const bf16* __restrict__ h_hi, const bf16* __restrict__ h_lo,
    bf16* __restrict__ outv_hi, bf16* __restrict__ outv_lo,
    const float* __restrict__ outW,
    const float* __restrict__ outb,
    float* __restrict__ outFinal,
    int Mtot)
{
    __shared__ float sScore[T], sX[T], sSrt[T], sAtt[T];
    __shared__ float sTau, sMax;
    __shared__ float sDoc[512];
    int tid = threadIdx.x;
    int n = blockIdx.x;
    size_t hbase = (size_t)n * T * HD2;

    if (tid < T) {
        float s = 0.f;
#pragma unroll
        for (int jb = 0; jb < 8; jb++) s += part[(size_t)jb * Mtot + n * T + tid];
        sScore[tid] = s;
    }
    __syncthreads();
    if (tid == 0) {
        float mx = sScore[0];
        for (int t = 1; t < T; t++) mx = fmaxf(mx, sScore[t]);
        sMax = mx;
    }
    __syncthreads();
    if (tid < T) {
        float x = sScore[tid] - sMax;
        sX[tid] = x;
        int rank = 0;
        for (int u = 0; u < T; u++){
            float xu = sScore[u] - sMax;
            if (xu > x || (xu == x && u < tid)) rank++;
        }
        sSrt[rank] = x;
    }
    __syncthreads();
    if (tid == 0) {
        float cs = -1.f; int supp = 0; float csAt = 0.f;
        for (int k = 0; k < T; k++){
            cs += sSrt[k];
            if ((float)(k + 1) * sSrt[k] > cs) { supp = k + 1; csAt = cs; }
        }
        sTau = csAt / (float)supp;
    }
    __syncthreads();
    if (tid < T) sAtt[tid] = fmaxf(sX[tid] - sTau, 0.f);
    __syncthreads();
    {
        int jj = tid * 2;
        float ax = 0.f, ay = 0.f;
#pragma unroll 8
        for (int t = 0; t < T; t++){
            size_t off = hbase + (size_t)t * HD2 + jj;
            uint32_t ph = *(const uint32_t*)&h_hi[off];
            uint32_t pl = *(const uint32_t*)&h_lo[off];
            __nv_bfloat162 bh = *(__nv_bfloat162*)&ph;
            __nv_bfloat162 bl = *(__nv_bfloat162*)&pl;
            float hx = __bfloat162float(bh.x) + __bfloat162float(bl.x);
            float hy = __bfloat162float(bh.y) + __bfloat162float(bl.y);
            float a = sAtt[t];
            ax += a * hx; ay += a * hy;
        }
        if (FINAL){ sDoc[jj] = ax; sDoc[jj + 1] = ay; }
        else {
            size_t o = (size_t)n * HD2 + jj;
            bf16 hx = __float2bfloat16_rn(ax);
            bf16 hy = __float2bfloat16_rn(ay);
            __nv_bfloat162 hp = __halves2bfloat162(hx, hy);
            __nv_bfloat162 lp = __halves2bfloat162(
                __float2bfloat16_rn(ax - __bfloat162float(hx)),
                __float2bfloat16_rn(ay - __bfloat162float(hy)));
            *(uint32_t*)&outv_hi[o] = *(uint32_t*)&hp;
            *(uint32_t*)&outv_lo[o] = *(uint32_t*)&lp;
        }
    }
    if (FINAL) {
        __syncthreads();
        if (tid < 10) {
            float s = outb[tid];
            for (int jj2 = 0; jj2 < 512; jj2++) s += sDoc[jj2] * outW[jj2 * 10 + tid];
            outFinal[n * 10 + tid] = s;
        }
    }
}

extern "C" void kernel_launch(void* const* d_in, const int* in_sizes, int n_in,
                              void* d_out, int out_size) {
    const int*   tokens  = (const int*)  d_in[0];
    const float* emb     = (const float*)d_in[1];
    const float* w_Wx_f  = (const float*)d_in[2];
    const float* w_Wh_f  = (const float*)d_in[3];
    const float* w_bx_f  = (const float*)d_in[4];
    const float* w_bh_f  = (const float*)d_in[5];
    const float* w_Wx_b  = (const float*)d_in[6];
    const float* w_Wh_b  = (const float*)d_in[7];
    const float* w_bx_b  = (const float*)d_in[8];
    const float* w_bh_b  = (const float*)d_in[9];
    const float* w_lin_W = (const float*)d_in[10];
    const float* w_lin_b = (const float*)d_in[11];
    const float* w_ctx   = (const float*)d_in[12];
    const float* s_Wx_f  = (const float*)d_in[13];
    const float* s_Wh_f  = (const float*)d_in[14];
    const float* s_bx_f  = (const float*)d_in[15];
    const float* s_bh_f  = (const float*)d_in[16];
    const float* s_Wx_b  = (const float*)d_in[17];
    const float* s_Wh_b  = (const float*)d_in[18];
    const float* s_bx_b  = (const float*)d_in[19];
    const float* s_bh_b  = (const float*)d_in[20];
    const float* s_lin_W = (const float*)d_in[21];
    const float* s_lin_b = (const float*)d_in[22];
    const float* s_ctx   = (const float*)d_in[23];
    const float* out_W   = (const float*)d_in[24];
    const float* out_b   = (const float*)d_in[25];
    float* out = (float*)d_out;

    int V = in_sizes[1] / EDIM;

    float *p_xg, *p_xg2;
    float4 *p_whp, *p_whp2;
    bf16 *p_embH, *p_embL, *p_wxH, *p_wxL, *p_linH, *p_linL;
    bf16 *p_swxH, *p_swxL, *p_slinH, *p_slinL;
    bf16 *p_hbH, *p_hbL, *p_sbH, *p_sbL, *p_h2bH, *p_h2bL;
    cudaGetSymbolAddress((void**)&p_xg,   g_xg);
    cudaGetSymbolAddress((void**)&p_xg2,  g_xg2);
    cudaGetSymbolAddress((void**)&p_whp,  g_whp);
    cudaGetSymbolAddress((void**)&p_whp2, g_whp2);
    cudaGetSymbolAddress((void**)&p_embH, g_embC_hi);  cudaGetSymbolAddress((void**)&p_embL, g_embC_lo);
    cudaGetSymbolAddress((void**)&p_wxH,  g_wxC_hi);   cudaGetSymbolAddress((void**)&p_wxL,  g_wxC_lo);
    cudaGetSymbolAddress((void**)&p_linH, g_linC_hi);  cudaGetSymbolAddress((void**)&p_linL, g_linC_lo);
    cudaGetSymbolAddress((void**)&p_swxH, g_swxC_hi);  cudaGetSymbolAddress((void**)&p_swxL, g_swxC_lo);
    cudaGetSymbolAddress((void**)&p_slinH,g_slinC_hi); cudaGetSymbolAddress((void**)&p_slinL,g_slinC_lo);
    cudaGetSymbolAddress((void**)&p_hbH,  g_hb_hi);    cudaGetSymbolAddress((void**)&p_hbL,  g_hb_lo);
    cudaGetSymbolAddress((void**)&p_sbH,  g_sb_hi);    cudaGetSymbolAddress((void**)&p_sbL,  g_sb_lo);
    cudaGetSymbolAddress((void**)&p_h2bH, g_h2b_hi);   cudaGetSymbolAddress((void**)&p_h2bL, g_h2b_lo);

    cudaFuncSetAttribute(mma2_kernel<false>, cudaFuncAttributeMaxDynamicSharedMemorySize, GSMEM);
    cudaFuncSetAttribute(mma2_kernel<true>,  cudaFuncAttributeMaxDynamicSharedMemorySize, GSMEM);

    // 0. one-time conversions / repacks
    repack_wh_kernel<<<dim3(256,2), 256>>>(w_Wh_f, w_Wh_b, p_whp);
    repack_wh_kernel<<<dim3(256,2), 256>>>(s_Wh_f, s_Wh_b, p_whp2);
    {
        long long tot = (long long)V * EKP;
        conv_splitA_kernel<<<(unsigned)((tot + 255) / 256), 256>>>(emb, p_embH, p_embL, EDIM, EKP, tot);
    }
    conv_splitB_kernel<<<(EKP*HD3 + 255)/256, 256>>>(w_Wx_f, p_wxH,            p_wxL,            EDIM, EKP, HD3);
    conv_splitB_kernel<<<(EKP*HD3 + 255)/256, 256>>>(w_Wx_b, p_wxH + EKP*HD3,  p_wxL + EKP*HD3,  EDIM, EKP, HD3);
    conv_splitB_kernel<<<(HD2*HD2 + 255)/256, 256>>>(w_lin_W, p_linH, p_linL, HD2, HD2, HD2);
    conv_splitB_kernel<<<(HD2*HD3 + 255)/256, 256>>>(s_Wx_f, p_swxH,           p_swxL,           HD2, HD2, HD3);
    conv_splitB_kernel<<<(HD2*HD3 + 255)/256, 256>>>(s_Wx_b, p_swxH + HD2*HD3, p_swxL + HD2*HD3, HD2, HD2, HD3);
    conv_splitB_kernel<<<(HD2*HD2 + 255)/256, 256>>>(s_lin_W, p_slinH, p_slinL, HD2, HD2, HD2);
    // 1. word input gates (embedding gather fused)
    mma2_kernel<false><<<dim3(MWORD/128, 12), 256, GSMEM>>>(
        p_embH, p_embL, tokens, EKP, p_wxH, p_wxL, w_bx_f, w_bx_b, nullptr, p_xg, MWORD, 6);
    // 2. word BiGRU scan
    gru_scan_kernel<TW, 8><<<(NWSEQ/8)*2, 256>>>(
        p_xg, p_hbH, p_hbL, p_whp, w_bh_f, w_bh_b, NWSEQ);
    // 3. word rep GEMM fused into scores (partials into g_xg: 8 slots)
    mma2_kernel<true><<<dim3(MWORD/128, 4), 256, GSMEM>>>(
        p_hbH, p_hbL, nullptr, HD2, p_linH, p_linL, w_lin_b, w_lin_b, w_ctx, p_xg, MWORD, 4);
    // 4. word attention epilogue -> sentence vectors (bf16-split direct)
    attn_epi_kernel<TW, false><<<NWSEQ, 256>>>(
        p_xg, p_hbH, p_hbL, p_sbH, p_sbL, nullptr, nullptr, nullptr, MWORD);
    // 5. sentence input gates
    mma2_kernel<false><<<dim3(MSENT/128, 12), 256, GSMEM>>>(
        p_sbH, p_sbL, nullptr, HD2, p_swxH, p_swxL, s_bx_f, s_bx_b, nullptr, p_xg2, MSENT, 6);
    // 6. sentence BiGRU scan
    gru_scan_kernel<TSENT, 2><<<(NDOC/2)*2, 256>>>(
        p_xg2, p_h2bH, p_h2bL, p_whp2, s_bh_f, s_bh_b, NDOC);
    // 7. sentence rep+score GEMM (partials into g_xg2)
    mma2_kernel<true><<<dim3(MSENT/128, 4), 256, GSMEM>>>(
        p_h2bH, p_h2bL, nullptr, HD2, p_slinH, p_slinL, s_lin_b, s_lin_b, s_ctx, p_xg2, MSENT, 4);
    // 8. sentence attention + final classifier
    attn_epi_kernel<TSENT, true><<<NDOC, 256>>>(
        p_xg2, p_h2bH, p_h2bL, nullptr, nullptr, out_W, out_b, out, MSENT);
}